// round 1
// baseline (speedup 1.0000x reference)
#include <cuda_runtime.h>
#include <math.h>

#define MAXN     50000
#define MAXE     1600000
#define IN_DIM   1024
#define HID      128
#define MAXG     64
#define MAXETOT  (MAXE + MAXN)

// ---------------- device scratch (static; no allocations) ----------------
__device__ float g_h[(size_t)MAXN * HID];     // h = x @ W
__device__ float g_out[(size_t)MAXN * HID];   // aggregated output per node
__device__ float g_e[MAXETOT];                // per-edge e, then p (reused)
__device__ float g_m[MAXN];                   // segment max
__device__ float g_den[MAXN];                 // segment sum
__device__ float g_asrc[MAXN];
__device__ float g_adst[MAXN];

// ---------------- helpers ----------------
__device__ __forceinline__ void atomicMaxFloat(float* addr, float val) {
    // works for arbitrary-sign floats: positive floats compare as signed ints,
    // negative floats compare reversed as unsigned ints.
    if (val >= 0.f) atomicMax((int*)addr, __float_as_int(val));
    else            atomicMin((unsigned int*)addr, __float_as_uint(val));
}

// ---------------- kernels ----------------

// init: g_out=0, g_m=-inf, g_den=0, pool(d_out)=0
__global__ void init_kernel(float* pool, int N) {
    int i = blockIdx.x * blockDim.x + threadIdx.x;
    int total = N * HID;
    if (i < total) g_out[i] = 0.f;
    if (i < N) { g_m[i] = -INFINITY; g_den[i] = 0.f; }
    if (i < MAXG * HID) pool[i] = 0.f;
}

// SGEMM: g_h[M,128] = A[M,1024] @ B[1024,128]
// BM=128, BN=128 (=HID), BK=8, 256 threads, 8x8 microtile per thread.
__global__ __launch_bounds__(256) void gemm_kernel(const float* __restrict__ A,
                                                   const float* __restrict__ B,
                                                   int M) {
    __shared__ float As[8][128];
    __shared__ float Bs[8][128];

    const int tid = threadIdx.x;
    const int tx = tid & 15;          // 0..15  -> col group
    const int ty = tid >> 4;          // 0..15  -> row group
    const int block_row = blockIdx.x * 128;

    // A tile load mapping: 128 rows x 8 cols = 1024 floats -> 4/thread (float4)
    const int arow = tid >> 1;            // 0..127
    const int acol = (tid & 1) * 4;       // 0 or 4
    // B tile load mapping: 8 rows x 128 cols -> 4/thread (float4), coalesced
    const int brow = tid >> 5;            // 0..7
    const int bcol = (tid & 31) * 4;      // 0..124

    float acc[8][8];
#pragma unroll
    for (int i = 0; i < 8; i++)
#pragma unroll
        for (int j = 0; j < 8; j++) acc[i][j] = 0.f;

    for (int k0 = 0; k0 < IN_DIM; k0 += 8) {
        float4 av = make_float4(0.f, 0.f, 0.f, 0.f);
        int gr = block_row + arow;
        if (gr < M)
            av = *(const float4*)(A + (size_t)gr * IN_DIM + k0 + acol);
        As[acol + 0][arow] = av.x;
        As[acol + 1][arow] = av.y;
        As[acol + 2][arow] = av.z;
        As[acol + 3][arow] = av.w;

        float4 bv = *(const float4*)(B + (size_t)(k0 + brow) * HID + bcol);
        *(float4*)&Bs[brow][bcol] = bv;

        __syncthreads();

#pragma unroll
        for (int k = 0; k < 8; k++) {
            float a[8], b[8];
#pragma unroll
            for (int i = 0; i < 8; i++) a[i] = As[k][ty * 8 + i];
#pragma unroll
            for (int j = 0; j < 8; j++) b[j] = Bs[k][tx * 8 + j];
#pragma unroll
            for (int i = 0; i < 8; i++)
#pragma unroll
                for (int j = 0; j < 8; j++)
                    acc[i][j] = fmaf(a[i], b[j], acc[i][j]);
        }
        __syncthreads();
    }

#pragma unroll
    for (int i = 0; i < 8; i++) {
        int r = block_row + ty * 8 + i;
        if (r < M) {
#pragma unroll
            for (int j = 0; j < 8; j += 4) {
                float4 v = make_float4(acc[i][j], acc[i][j + 1],
                                       acc[i][j + 2], acc[i][j + 3]);
                *(float4*)(g_h + (size_t)r * HID + tx * 8 + j) = v;
            }
        }
    }
}

// a_src[n] = h[n]·att_src ; a_dst[n] = h[n]·att_dst (one warp per node)
__global__ void attdot_kernel(const float* __restrict__ att_src,
                              const float* __restrict__ att_dst, int N) {
    int warp = (blockIdx.x * blockDim.x + threadIdx.x) >> 5;
    int lane = threadIdx.x & 31;
    if (warp >= N) return;
    float4 hv = ((const float4*)g_h)[(size_t)warp * 32 + lane];
    float4 s4 = ((const float4*)att_src)[lane];
    float4 d4 = ((const float4*)att_dst)[lane];
    float ps = hv.x * s4.x + hv.y * s4.y + hv.z * s4.z + hv.w * s4.w;
    float pd = hv.x * d4.x + hv.y * d4.y + hv.z * d4.z + hv.w * d4.w;
#pragma unroll
    for (int o = 16; o; o >>= 1) {
        ps += __shfl_xor_sync(0xffffffffu, ps, o);
        pd += __shfl_xor_sync(0xffffffffu, pd, o);
    }
    if (lane == 0) { g_asrc[warp] = ps; g_adst[warp] = pd; }
}

// pass A: e = leaky_relu(a_src[s] + a_dst[d]); segment max into g_m[d]
__global__ void edgeA_kernel(const int* __restrict__ ei, int E, int N) {
    int i = blockIdx.x * blockDim.x + threadIdx.x;
    int tot = E + N;
    if (i >= tot) return;
    int s, d;
    if (i < E) { s = ei[i]; d = ei[E + i]; }
    else       { s = d = i - E; }
    float e = g_asrc[s] + g_adst[d];
    e = e > 0.f ? e : 0.2f * e;
    g_e[i] = e;
    atomicMaxFloat(&g_m[d], e);
}

// pass B: p = exp(e - m[d]); segment sum into g_den[d]; store p in g_e
__global__ void edgeB_kernel(const int* __restrict__ ei, int E, int N) {
    int i = blockIdx.x * blockDim.x + threadIdx.x;
    int tot = E + N;
    if (i >= tot) return;
    int d = (i < E) ? ei[E + i] : (i - E);
    float p = expf(g_e[i] - g_m[d]);
    g_e[i] = p;
    atomicAdd(&g_den[d], p);
}

// pass C: out[d] += alpha * h[s]   (one warp per edge, vector red.add)
__global__ __launch_bounds__(256) void edgeC_kernel(const int* __restrict__ ei,
                                                    int E, int N) {
    int warp = (blockIdx.x * blockDim.x + threadIdx.x) >> 5;
    int lane = threadIdx.x & 31;
    int tot = E + N;
    if (warp >= tot) return;
    int s, d;
    if (warp < E) { s = ei[warp]; d = ei[E + warp]; }
    else          { s = d = warp - E; }
    float alpha = g_e[warp] / g_den[d];
    float4 hv = ((const float4*)g_h)[(size_t)s * 32 + lane];
    float* dst = g_out + (size_t)d * HID + lane * 4;
    asm volatile("red.global.add.v4.f32 [%0], {%1,%2,%3,%4};"
                 :: "l"(dst),
                    "f"(alpha * hv.x), "f"(alpha * hv.y),
                    "f"(alpha * hv.z), "f"(alpha * hv.w)
                 : "memory");
}

// pass D: out = relu(out + bias); pool[batch[n]] = max(pool, out[n])
__global__ void finalize_kernel(const float* __restrict__ bias,
                                const int* __restrict__ batch,
                                float* pool, int N) {
    int i = blockIdx.x * blockDim.x + threadIdx.x;  // over N*32 float4 lanes
    if (i >= N * 32) return;
    int node = i >> 5;
    int c4 = i & 31;
    float4 v = ((const float4*)g_out)[i];
    float4 b = ((const float4*)bias)[c4];
    v.x = fmaxf(v.x + b.x, 0.f);
    v.y = fmaxf(v.y + b.y, 0.f);
    v.z = fmaxf(v.z + b.z, 0.f);
    v.w = fmaxf(v.w + b.w, 0.f);
    int g = batch[node];
    int* p = (int*)(pool + (size_t)g * HID + c4 * 4);
    // values >= 0 so signed-int compare is order-preserving
    atomicMax(p + 0, __float_as_int(v.x));
    atomicMax(p + 1, __float_as_int(v.y));
    atomicMax(p + 2, __float_as_int(v.z));
    atomicMax(p + 3, __float_as_int(v.w));
}

// ---------------- launch ----------------
extern "C" void kernel_launch(void* const* d_in, const int* in_sizes, int n_in,
                              void* d_out, int out_size) {
    const float* x       = (const float*)d_in[0];   // [N, 1024]
    const float* W       = (const float*)d_in[1];   // [1024, 128]
    const float* att_src = (const float*)d_in[2];   // [128]
    const float* att_dst = (const float*)d_in[3];   // [128]
    const float* bias    = (const float*)d_in[4];   // [128]
    const int*   ei      = (const int*)d_in[5];     // [2, E]
    const int*   batch   = (const int*)d_in[6];     // [N]
    float* pool = (float*)d_out;                    // [G, 128]

    const int N = in_sizes[0] / IN_DIM;
    const int E = in_sizes[5] / 2;
    const int tot = E + N;

    // init
    {
        int total = N * HID;
        init_kernel<<<(total + 255) / 256, 256>>>(pool, N);
    }
    // GEMM h = x @ W
    gemm_kernel<<<(N + 127) / 128, 256>>>(x, W, N);
    // a_src / a_dst
    attdot_kernel<<<(N * 32 + 255) / 256, 256>>>(att_src, att_dst, N);
    // edge passes
    edgeA_kernel<<<(tot + 255) / 256, 256>>>(ei, E, N);
    edgeB_kernel<<<(tot + 255) / 256, 256>>>(ei, E, N);
    edgeC_kernel<<<(tot * 32 + 255) / 256, 256>>>(ei, E, N);
    // finalize + global max pool
    finalize_kernel<<<(N * 32 + 255) / 256, 256>>>(bias, batch, pool, N);
}

// round 2
// speedup vs baseline: 1.5053x; 1.5053x over previous
#include <cuda_runtime.h>
#include <math.h>

#define MAXN     50000
#define MAXE     1600000
#define IN_DIM   1024
#define HID      128
#define MAXG     64
#define MAXETOT  (MAXE + MAXN)
#define NKB      (IN_DIM / 16)   // 64 k-blocks of 16

// ---------------- device scratch (static; no allocations) ----------------
__device__ float g_h[(size_t)MAXN * HID];     // h = x @ W
__device__ float g_out[(size_t)MAXN * HID];   // aggregated output per node
__device__ float g_e[MAXETOT];                // per-edge e, then p (reused)
__device__ float g_m[MAXN];                   // segment max
__device__ float g_den[MAXN];                 // segment sum
__device__ float g_asrc[MAXN];
__device__ float g_adst[MAXN];
__device__ float2 g_Wp[NKB * 8 * 128];        // W permuted: [kb][slot][n] pairs (k,k+4), tf32-rounded

// ---------------- helpers ----------------
__device__ __forceinline__ void atomicMaxFloat(float* addr, float val) {
    if (val >= 0.f) atomicMax((int*)addr, __float_as_int(val));
    else            atomicMin((unsigned int*)addr, __float_as_uint(val));
}

__device__ __forceinline__ float tf32r(float x) {
    unsigned int t;
    asm("cvt.rna.tf32.f32 %0, %1;" : "=r"(t) : "f"(x));
    return __uint_as_float(t);
}

// ---------------- kernels ----------------

// init: g_out=0, g_m=-inf, g_den=0, pool(d_out)=0
__global__ void init_kernel(float* pool, int N) {
    int i = blockIdx.x * blockDim.x + threadIdx.x;
    int total = N * HID;
    if (i < total) g_out[i] = 0.f;
    if (i < N) { g_m[i] = -INFINITY; g_den[i] = 0.f; }
    if (i < MAXG * HID) pool[i] = 0.f;
}

// W preprocess: Wp[kb][s][n] = (tf32(W[kb*16+ks][n]), tf32(W[kb*16+ks+4][n]))
// where ks = (s>>2)*8 + (s&3). This makes B mma fragments single float2 LDS.
__global__ void prepW_kernel(const float* __restrict__ W) {
    int idx = blockIdx.x * blockDim.x + threadIdx.x;
    if (idx >= NKB * 8 * 128) return;
    int n = idx & 127;
    int s = (idx >> 7) & 7;
    int kb = idx >> 10;
    int ks = ((s >> 2) << 3) + (s & 3);
    int k0 = kb * 16 + ks;
    g_Wp[idx] = make_float2(tf32r(W[(size_t)k0 * HID + n]),
                            tf32r(W[(size_t)(k0 + 4) * HID + n]));
}

// TF32 tensor-core GEMM: g_h[M,128] = A[M,1024] @ W[1024,128]
// BM=128, BN=128, BK=16, 256 threads, 8 warps (4m x 2n), warp tile 32x64.
__global__ __launch_bounds__(256) void gemm_tf32_kernel(const float* __restrict__ A,
                                                        int M) {
    // As: pair-permuted, f2 slots 0..7 per row, padded to 10 f2 (5 f4) per row
    __shared__ float4 As[2][128 * 5];
    // Bs: [slot][n], n-stride padded to 132 f2
    __shared__ float2 Bs[2][8 * 132];

    const int tid  = threadIdx.x;
    const int lane = tid & 31;
    const int warp = tid >> 5;
    const int gid  = lane >> 2;   // 0..7
    const int tig  = lane & 3;    // 0..3
    const int wm   = (warp & 3) * 32;   // warp m-offset
    const int wn   = (warp >> 2) * 64;  // warp n-offset
    const int block_row = blockIdx.x * 128;

    // A global load mapping: thread covers row (tid>>1), k-half (tid&1)*8
    const int ar = tid >> 1;
    const int ah = tid & 1;
    const bool avalid = (block_row + ar) < M;
    const float* aptr = A + (size_t)(block_row + ar) * IN_DIM + ah * 8;

    // B tile load: 1024 f2 per kb, thread takes 4 f2 (2 float4)
    const float4* wp4 = (const float4*)g_Wp;

    float acc[2][8][4];
#pragma unroll
    for (int mt = 0; mt < 2; mt++)
#pragma unroll
        for (int nt = 0; nt < 8; nt++)
#pragma unroll
            for (int i = 0; i < 4; i++) acc[mt][nt][i] = 0.f;

    float4 a0v, a1v, b0v, b1v;

    // ---- prologue: load kb=0 ----
    if (avalid) {
        a0v = *(const float4*)(aptr);
        a1v = *(const float4*)(aptr + 4);
    } else {
        a0v = a1v = make_float4(0.f, 0.f, 0.f, 0.f);
    }
    b0v = wp4[(size_t)tid * 2];
    b1v = wp4[(size_t)tid * 2 + 1];
    {
        float4 p0 = make_float4(tf32r(a0v.x), tf32r(a1v.x), tf32r(a0v.y), tf32r(a1v.y));
        float4 p1 = make_float4(tf32r(a0v.z), tf32r(a1v.z), tf32r(a0v.w), tf32r(a1v.w));
        As[0][ar * 5 + ah * 2 + 0] = p0;
        As[0][ar * 5 + ah * 2 + 1] = p1;
        float4* bsts = (float4*)&Bs[0][warp * 132 + (tid & 31) * 4];
        bsts[0] = b0v;
        bsts[1] = b1v;
    }
    __syncthreads();

#pragma unroll 1
    for (int kb = 0; kb < NKB; kb++) {
        const int buf = kb & 1;

        // prefetch next tile from global
        if (kb < NKB - 1) {
            if (avalid) {
                a0v = *(const float4*)(aptr + (kb + 1) * 16);
                a1v = *(const float4*)(aptr + (kb + 1) * 16 + 4);
            }
            size_t bbase = (size_t)(kb + 1) * 512;   // f4 units per kb tile
            b0v = wp4[bbase + tid * 2];
            b1v = wp4[bbase + tid * 2 + 1];
        }

        // compute on smem[buf]
        const float2* Asf2 = (const float2*)As[buf];
        const float2* Bsf2 = Bs[buf];
#pragma unroll
        for (int ks = 0; ks < 2; ks++) {
            float2 afr[2][2];
#pragma unroll
            for (int mt = 0; mt < 2; mt++) {
                int r0 = wm + mt * 16 + gid;
                afr[mt][0] = Asf2[r0 * 10 + ks * 4 + tig];
                afr[mt][1] = Asf2[(r0 + 8) * 10 + ks * 4 + tig];
            }
            float2 bfr[8];
#pragma unroll
            for (int nt = 0; nt < 8; nt++)
                bfr[nt] = Bsf2[(ks * 4 + tig) * 132 + wn + nt * 8 + gid];
#pragma unroll
            for (int mt = 0; mt < 2; mt++)
#pragma unroll
                for (int nt = 0; nt < 8; nt++) {
                    asm("mma.sync.aligned.m16n8k8.row.col.f32.tf32.tf32.f32 "
                        "{%0,%1,%2,%3}, {%4,%5,%6,%7}, {%8,%9}, {%0,%1,%2,%3};"
                        : "+f"(acc[mt][nt][0]), "+f"(acc[mt][nt][1]),
                          "+f"(acc[mt][nt][2]), "+f"(acc[mt][nt][3])
                        : "r"(__float_as_uint(afr[mt][0].x)),
                          "r"(__float_as_uint(afr[mt][1].x)),
                          "r"(__float_as_uint(afr[mt][0].y)),
                          "r"(__float_as_uint(afr[mt][1].y)),
                          "r"(__float_as_uint(bfr[nt].x)),
                          "r"(__float_as_uint(bfr[nt].y)));
                }
        }

        // store next tile into the other buffer
        if (kb < NKB - 1) {
            float4 p0 = make_float4(tf32r(a0v.x), tf32r(a1v.x), tf32r(a0v.y), tf32r(a1v.y));
            float4 p1 = make_float4(tf32r(a0v.z), tf32r(a1v.z), tf32r(a0v.w), tf32r(a1v.w));
            float4* asts = &As[buf ^ 1][ar * 5 + ah * 2];
            asts[0] = p0;
            asts[1] = p1;
            float4* bsts = (float4*)&Bs[buf ^ 1][warp * 132 + (tid & 31) * 4];
            bsts[0] = b0v;
            bsts[1] = b1v;
            __syncthreads();
        }
    }

    // epilogue: write g_h
#pragma unroll
    for (int mt = 0; mt < 2; mt++) {
        int row0 = block_row + wm + mt * 16 + gid;
#pragma unroll
        for (int nt = 0; nt < 8; nt++) {
            int col = wn + nt * 8 + tig * 2;
            if (row0 < M)
                *(float2*)&g_h[(size_t)row0 * HID + col] =
                    make_float2(acc[mt][nt][0], acc[mt][nt][1]);
            if (row0 + 8 < M)
                *(float2*)&g_h[(size_t)(row0 + 8) * HID + col] =
                    make_float2(acc[mt][nt][2], acc[mt][nt][3]);
        }
    }
}

// a_src[n] = h[n]·att_src ; a_dst[n] = h[n]·att_dst (one warp per node)
__global__ void attdot_kernel(const float* __restrict__ att_src,
                              const float* __restrict__ att_dst, int N) {
    int warp = (blockIdx.x * blockDim.x + threadIdx.x) >> 5;
    int lane = threadIdx.x & 31;
    if (warp >= N) return;
    float4 hv = ((const float4*)g_h)[(size_t)warp * 32 + lane];
    float4 s4 = ((const float4*)att_src)[lane];
    float4 d4 = ((const float4*)att_dst)[lane];
    float ps = hv.x * s4.x + hv.y * s4.y + hv.z * s4.z + hv.w * s4.w;
    float pd = hv.x * d4.x + hv.y * d4.y + hv.z * d4.z + hv.w * d4.w;
#pragma unroll
    for (int o = 16; o; o >>= 1) {
        ps += __shfl_xor_sync(0xffffffffu, ps, o);
        pd += __shfl_xor_sync(0xffffffffu, pd, o);
    }
    if (lane == 0) { g_asrc[warp] = ps; g_adst[warp] = pd; }
}

// pass A: e = leaky_relu(a_src[s] + a_dst[d]); segment max into g_m[d]
__global__ void edgeA_kernel(const int* __restrict__ ei, int E, int N) {
    int i = blockIdx.x * blockDim.x + threadIdx.x;
    int tot = E + N;
    if (i >= tot) return;
    int s, d;
    if (i < E) { s = ei[i]; d = ei[E + i]; }
    else       { s = d = i - E; }
    float e = g_asrc[s] + g_adst[d];
    e = e > 0.f ? e : 0.2f * e;
    g_e[i] = e;
    atomicMaxFloat(&g_m[d], e);
}

// pass B: p = exp(e - m[d]); segment sum into g_den[d]; store p in g_e
__global__ void edgeB_kernel(const int* __restrict__ ei, int E, int N) {
    int i = blockIdx.x * blockDim.x + threadIdx.x;
    int tot = E + N;
    if (i >= tot) return;
    int d = (i < E) ? ei[E + i] : (i - E);
    float p = expf(g_e[i] - g_m[d]);
    g_e[i] = p;
    atomicAdd(&g_den[d], p);
}

// pass C: out[d] += alpha * h[s]   (one warp per edge, vector red.add)
__global__ __launch_bounds__(256) void edgeC_kernel(const int* __restrict__ ei,
                                                    int E, int N) {
    int warp = (blockIdx.x * blockDim.x + threadIdx.x) >> 5;
    int lane = threadIdx.x & 31;
    int tot = E + N;
    if (warp >= tot) return;
    int s, d;
    if (warp < E) { s = ei[warp]; d = ei[E + warp]; }
    else          { s = d = warp - E; }
    float alpha = g_e[warp] / g_den[d];
    float4 hv = ((const float4*)g_h)[(size_t)s * 32 + lane];
    float* dst = g_out + (size_t)d * HID + lane * 4;
    asm volatile("red.global.add.v4.f32 [%0], {%1,%2,%3,%4};"
                 :: "l"(dst),
                    "f"(alpha * hv.x), "f"(alpha * hv.y),
                    "f"(alpha * hv.z), "f"(alpha * hv.w)
                 : "memory");
}

// pass D: out = relu(out + bias); pool[batch[n]] = max(pool, out[n])
__global__ void finalize_kernel(const float* __restrict__ bias,
                                const int* __restrict__ batch,
                                float* pool, int N) {
    int i = blockIdx.x * blockDim.x + threadIdx.x;  // over N*32 float4 lanes
    if (i >= N * 32) return;
    int node = i >> 5;
    int c4 = i & 31;
    float4 v = ((const float4*)g_out)[i];
    float4 b = ((const float4*)bias)[c4];
    v.x = fmaxf(v.x + b.x, 0.f);
    v.y = fmaxf(v.y + b.y, 0.f);
    v.z = fmaxf(v.z + b.z, 0.f);
    v.w = fmaxf(v.w + b.w, 0.f);
    int g = batch[node];
    int* p = (int*)(pool + (size_t)g * HID + c4 * 4);
    atomicMax(p + 0, __float_as_int(v.x));
    atomicMax(p + 1, __float_as_int(v.y));
    atomicMax(p + 2, __float_as_int(v.z));
    atomicMax(p + 3, __float_as_int(v.w));
}

// ---------------- launch ----------------
extern "C" void kernel_launch(void* const* d_in, const int* in_sizes, int n_in,
                              void* d_out, int out_size) {
    const float* x       = (const float*)d_in[0];   // [N, 1024]
    const float* W       = (const float*)d_in[1];   // [1024, 128]
    const float* att_src = (const float*)d_in[2];   // [128]
    const float* att_dst = (const float*)d_in[3];   // [128]
    const float* bias    = (const float*)d_in[4];   // [128]
    const int*   ei      = (const int*)d_in[5];     // [2, E]
    const int*   batch   = (const int*)d_in[6];     // [N]
    float* pool = (float*)d_out;                    // [G, 128]

    const int N = in_sizes[0] / IN_DIM;
    const int E = in_sizes[5] / 2;
    const int tot = E + N;

    // init + W preprocess
    {
        int total = N * HID;
        init_kernel<<<(total + 255) / 256, 256>>>(pool, N);
        prepW_kernel<<<(NKB * 8 * 128 + 255) / 256, 256>>>(W);
    }
    // GEMM h = x @ W (tf32 tensor cores)
    gemm_tf32_kernel<<<(N + 127) / 128, 256>>>(x, N);
    // a_src / a_dst
    attdot_kernel<<<(N * 32 + 255) / 256, 256>>>(att_src, att_dst, N);
    // edge passes
    edgeA_kernel<<<(tot + 255) / 256, 256>>>(ei, E, N);
    edgeB_kernel<<<(tot + 255) / 256, 256>>>(ei, E, N);
    edgeC_kernel<<<(tot * 32 + 255) / 256, 256>>>(ei, E, N);
    // finalize + global max pool
    finalize_kernel<<<(N * 32 + 255) / 256, 256>>>(bias, batch, pool, N);
}

// round 3
// speedup vs baseline: 1.7112x; 1.1368x over previous
#include <cuda_runtime.h>
#include <math.h>

#define MAXN     50000
#define MAXE     1600000
#define IN_DIM   1024
#define HID      128
#define MAXG     64
#define MAXETOT  (MAXE + MAXN)
#define NKB      (IN_DIM / 16)   // 64 k-blocks of 16
#define SCAN_T   1024

// ---------------- device scratch (static; no allocations) ----------------
__device__ float g_h[(size_t)MAXN * HID];     // h = x @ W
__device__ float g_e[MAXETOT];                // per-edge e then p, CSR order
__device__ float g_asrc[MAXN];
__device__ float g_adst[MAXN];
__device__ int   g_cnt[MAXN];                 // per-dst degree (incl self loop)
__device__ int   g_off[MAXN + 1];             // CSR offsets
__device__ int   g_cur[MAXN];                 // scatter cursors
__device__ int   g_csr_src[MAXETOT];          // src ids grouped by dst
__device__ float2 g_Wp[NKB * 8 * 128];        // W permuted tf32 pairs

// ---------------- helpers ----------------
__device__ __forceinline__ float tf32r(float x) {
    unsigned int t;
    asm("cvt.rna.tf32.f32 %0, %1;" : "=r"(t) : "f"(x));
    return __uint_as_float(t);
}

// ---------------- kernels ----------------

// init: pool = 0, g_cnt = 1 (self loop pre-counted)
__global__ void init_kernel(float* pool, int N) {
    int i = blockIdx.x * blockDim.x + threadIdx.x;
    if (i < N) g_cnt[i] = 1;
    if (i < MAXG * HID) pool[i] = 0.f;
}

// W preprocess: Wp[kb][s][n] = (tf32(W[kb*16+ks][n]), tf32(W[kb*16+ks+4][n]))
__global__ void prepW_kernel(const float* __restrict__ W) {
    int idx = blockIdx.x * blockDim.x + threadIdx.x;
    if (idx >= NKB * 8 * 128) return;
    int n = idx & 127;
    int s = (idx >> 7) & 7;
    int kb = idx >> 10;
    int ks = ((s >> 2) << 3) + (s & 3);
    int k0 = kb * 16 + ks;
    g_Wp[idx] = make_float2(tf32r(W[(size_t)k0 * HID + n]),
                            tf32r(W[(size_t)(k0 + 4) * HID + n]));
}

// TF32 tensor-core GEMM: g_h[M,128] = A[M,1024] @ W[1024,128]
__global__ __launch_bounds__(256) void gemm_tf32_kernel(const float* __restrict__ A,
                                                        int M) {
    __shared__ float4 As[2][128 * 5];
    __shared__ float2 Bs[2][8 * 132];

    const int tid  = threadIdx.x;
    const int lane = tid & 31;
    const int warp = tid >> 5;
    const int gid  = lane >> 2;
    const int tig  = lane & 3;
    const int wm   = (warp & 3) * 32;
    const int wn   = (warp >> 2) * 64;
    const int block_row = blockIdx.x * 128;

    const int ar = tid >> 1;
    const int ah = tid & 1;
    const bool avalid = (block_row + ar) < M;
    const float* aptr = A + (size_t)(block_row + ar) * IN_DIM + ah * 8;
    const float4* wp4 = (const float4*)g_Wp;

    float acc[2][8][4];
#pragma unroll
    for (int mt = 0; mt < 2; mt++)
#pragma unroll
        for (int nt = 0; nt < 8; nt++)
#pragma unroll
            for (int i = 0; i < 4; i++) acc[mt][nt][i] = 0.f;

    float4 a0v, a1v, b0v, b1v;
    if (avalid) {
        a0v = *(const float4*)(aptr);
        a1v = *(const float4*)(aptr + 4);
    } else {
        a0v = a1v = make_float4(0.f, 0.f, 0.f, 0.f);
    }
    b0v = wp4[(size_t)tid * 2];
    b1v = wp4[(size_t)tid * 2 + 1];
    {
        float4 p0 = make_float4(tf32r(a0v.x), tf32r(a1v.x), tf32r(a0v.y), tf32r(a1v.y));
        float4 p1 = make_float4(tf32r(a0v.z), tf32r(a1v.z), tf32r(a0v.w), tf32r(a1v.w));
        As[0][ar * 5 + ah * 2 + 0] = p0;
        As[0][ar * 5 + ah * 2 + 1] = p1;
        float4* bsts = (float4*)&Bs[0][warp * 132 + (tid & 31) * 4];
        bsts[0] = b0v;
        bsts[1] = b1v;
    }
    __syncthreads();

#pragma unroll 1
    for (int kb = 0; kb < NKB; kb++) {
        const int buf = kb & 1;
        if (kb < NKB - 1) {
            if (avalid) {
                a0v = *(const float4*)(aptr + (kb + 1) * 16);
                a1v = *(const float4*)(aptr + (kb + 1) * 16 + 4);
            }
            size_t bbase = (size_t)(kb + 1) * 512;
            b0v = wp4[bbase + tid * 2];
            b1v = wp4[bbase + tid * 2 + 1];
        }

        const float2* Asf2 = (const float2*)As[buf];
        const float2* Bsf2 = Bs[buf];
#pragma unroll
        for (int ks = 0; ks < 2; ks++) {
            float2 afr[2][2];
#pragma unroll
            for (int mt = 0; mt < 2; mt++) {
                int r0 = wm + mt * 16 + gid;
                afr[mt][0] = Asf2[r0 * 10 + ks * 4 + tig];
                afr[mt][1] = Asf2[(r0 + 8) * 10 + ks * 4 + tig];
            }
            float2 bfr[8];
#pragma unroll
            for (int nt = 0; nt < 8; nt++)
                bfr[nt] = Bsf2[(ks * 4 + tig) * 132 + wn + nt * 8 + gid];
#pragma unroll
            for (int mt = 0; mt < 2; mt++)
#pragma unroll
                for (int nt = 0; nt < 8; nt++) {
                    asm("mma.sync.aligned.m16n8k8.row.col.f32.tf32.tf32.f32 "
                        "{%0,%1,%2,%3}, {%4,%5,%6,%7}, {%8,%9}, {%0,%1,%2,%3};"
                        : "+f"(acc[mt][nt][0]), "+f"(acc[mt][nt][1]),
                          "+f"(acc[mt][nt][2]), "+f"(acc[mt][nt][3])
                        : "r"(__float_as_uint(afr[mt][0].x)),
                          "r"(__float_as_uint(afr[mt][1].x)),
                          "r"(__float_as_uint(afr[mt][0].y)),
                          "r"(__float_as_uint(afr[mt][1].y)),
                          "r"(__float_as_uint(bfr[nt].x)),
                          "r"(__float_as_uint(bfr[nt].y)));
                }
        }

        if (kb < NKB - 1) {
            float4 p0 = make_float4(tf32r(a0v.x), tf32r(a1v.x), tf32r(a0v.y), tf32r(a1v.y));
            float4 p1 = make_float4(tf32r(a0v.z), tf32r(a1v.z), tf32r(a0v.w), tf32r(a1v.w));
            float4* asts = &As[buf ^ 1][ar * 5 + ah * 2];
            asts[0] = p0;
            asts[1] = p1;
            float4* bsts = (float4*)&Bs[buf ^ 1][warp * 132 + (tid & 31) * 4];
            bsts[0] = b0v;
            bsts[1] = b1v;
            __syncthreads();
        }
    }

#pragma unroll
    for (int mt = 0; mt < 2; mt++) {
        int row0 = block_row + wm + mt * 16 + gid;
#pragma unroll
        for (int nt = 0; nt < 8; nt++) {
            int col = wn + nt * 8 + tig * 2;
            if (row0 < M)
                *(float2*)&g_h[(size_t)row0 * HID + col] =
                    make_float2(acc[mt][nt][0], acc[mt][nt][1]);
            if (row0 + 8 < M)
                *(float2*)&g_h[(size_t)(row0 + 8) * HID + col] =
                    make_float2(acc[mt][nt][2], acc[mt][nt][3]);
        }
    }
}

// a_src[n] = h[n]·att_src ; a_dst[n] = h[n]·att_dst (one warp per node)
__global__ void attdot_kernel(const float* __restrict__ att_src,
                              const float* __restrict__ att_dst, int N) {
    int warp = (blockIdx.x * blockDim.x + threadIdx.x) >> 5;
    int lane = threadIdx.x & 31;
    if (warp >= N) return;
    float4 hv = ((const float4*)g_h)[(size_t)warp * 32 + lane];
    float4 s4 = ((const float4*)att_src)[lane];
    float4 d4 = ((const float4*)att_dst)[lane];
    float ps = hv.x * s4.x + hv.y * s4.y + hv.z * s4.z + hv.w * s4.w;
    float pd = hv.x * d4.x + hv.y * d4.y + hv.z * d4.z + hv.w * d4.w;
#pragma unroll
    for (int o = 16; o; o >>= 1) {
        ps += __shfl_xor_sync(0xffffffffu, ps, o);
        pd += __shfl_xor_sync(0xffffffffu, pd, o);
    }
    if (lane == 0) { g_asrc[warp] = ps; g_adst[warp] = pd; }
}

// count incoming edges per dst (self loops pre-counted in init)
__global__ void count_kernel(const int* __restrict__ ei, int E) {
    int i = blockIdx.x * blockDim.x + threadIdx.x;
    if (i >= E) return;
    atomicAdd(&g_cnt[ei[E + i]], 1);
}

// single-block exclusive scan of g_cnt -> g_off (and cursors)
__global__ __launch_bounds__(SCAN_T) void scan_kernel(int N) {
    __shared__ int warpsum[32];
    int tid = threadIdx.x;
    int per = (N + SCAN_T - 1) / SCAN_T;
    int start = tid * per;
    int end = min(start + per, N);
    int sum = 0;
    for (int i = start; i < end; i++) sum += g_cnt[i];

    int lane = tid & 31, w = tid >> 5;
    int v = sum;
#pragma unroll
    for (int o = 1; o < 32; o <<= 1) {
        int t = __shfl_up_sync(0xffffffffu, v, o);
        if (lane >= o) v += t;
    }
    if (lane == 31) warpsum[w] = v;
    __syncthreads();
    if (w == 0) {
        int t = warpsum[lane];
#pragma unroll
        for (int o = 1; o < 32; o <<= 1) {
            int u = __shfl_up_sync(0xffffffffu, t, o);
            if (lane >= o) t += u;
        }
        warpsum[lane] = t;
    }
    __syncthreads();
    int excl = v - sum + (w > 0 ? warpsum[w - 1] : 0);

    int run = excl;
    for (int i = start; i < end; i++) {
        int c = g_cnt[i];
        g_off[i] = run;
        g_cur[i] = run;
        run += c;
    }
    if (start < N && end == N) g_off[N] = run;
}

// scatter edges (and self loops) into CSR order
__global__ void scatter_kernel(const int* __restrict__ ei, int E, int N) {
    int i = blockIdx.x * blockDim.x + threadIdx.x;
    int tot = E + N;
    if (i >= tot) return;
    int s, d;
    if (i < E) { s = ei[i]; d = ei[E + i]; }
    else       { s = d = i - E; }
    int pos = atomicAdd(&g_cur[d], 1);
    g_csr_src[pos] = s;
}

// fused GAT: warp per dst node. softmax over incoming edges, weighted
// aggregation, bias+relu, global max pool — all in one pass.
__global__ __launch_bounds__(256) void gat_kernel(const float* __restrict__ bias,
                                                  const int* __restrict__ batch,
                                                  float* pool, int N) {
    int node = (blockIdx.x * blockDim.x + threadIdx.x) >> 5;
    int lane = threadIdx.x & 31;
    if (node >= N) return;

    int base = g_off[node];
    int deg  = g_off[node + 1] - base;
    float adst = g_adst[node];

    // loop 1: e = leaky_relu(a_src[s] + a_dst[d]); warp max
    float m = -INFINITY;
    for (int j = lane; j < deg; j += 32) {
        int s = g_csr_src[base + j];
        float e = g_asrc[s] + adst;
        e = e > 0.f ? e : 0.2f * e;
        g_e[base + j] = e;
        m = fmaxf(m, e);
    }
#pragma unroll
    for (int o = 16; o; o >>= 1)
        m = fmaxf(m, __shfl_xor_sync(0xffffffffu, m, o));

    // loop 2: p = exp(e - m); warp sum
    float den = 0.f;
    for (int j = lane; j < deg; j += 32) {
        float p = __expf(g_e[base + j] - m);
        g_e[base + j] = p;
        den += p;
    }
#pragma unroll
    for (int o = 16; o; o >>= 1)
        den += __shfl_xor_sync(0xffffffffu, den, o);

    // loop 3: acc = sum p * h[s] (full warp loads each row)
    float4 acc = make_float4(0.f, 0.f, 0.f, 0.f);
    for (int j = 0; j < deg; j++) {
        float p = g_e[base + j];
        int s = g_csr_src[base + j];
        float4 hv = ((const float4*)g_h)[(size_t)s * 32 + lane];
        acc.x = fmaf(p, hv.x, acc.x);
        acc.y = fmaf(p, hv.y, acc.y);
        acc.z = fmaf(p, hv.z, acc.z);
        acc.w = fmaf(p, hv.w, acc.w);
    }

    float inv = 1.f / den;
    float4 b = ((const float4*)bias)[lane];
    float4 v;
    v.x = fmaxf(acc.x * inv + b.x, 0.f);
    v.y = fmaxf(acc.y * inv + b.y, 0.f);
    v.z = fmaxf(acc.z * inv + b.z, 0.f);
    v.w = fmaxf(acc.w * inv + b.w, 0.f);

    int g = batch[node];
    int* p = (int*)(pool + (size_t)g * HID + lane * 4);
    // values >= 0 so signed-int compare is order-preserving
    atomicMax(p + 0, __float_as_int(v.x));
    atomicMax(p + 1, __float_as_int(v.y));
    atomicMax(p + 2, __float_as_int(v.z));
    atomicMax(p + 3, __float_as_int(v.w));
}

// ---------------- launch ----------------
extern "C" void kernel_launch(void* const* d_in, const int* in_sizes, int n_in,
                              void* d_out, int out_size) {
    const float* x       = (const float*)d_in[0];   // [N, 1024]
    const float* W       = (const float*)d_in[1];   // [1024, 128]
    const float* att_src = (const float*)d_in[2];   // [128]
    const float* att_dst = (const float*)d_in[3];   // [128]
    const float* bias    = (const float*)d_in[4];   // [128]
    const int*   ei      = (const int*)d_in[5];     // [2, E]
    const int*   batch   = (const int*)d_in[6];     // [N]
    float* pool = (float*)d_out;                    // [G, 128]

    const int N = in_sizes[0] / IN_DIM;
    const int E = in_sizes[5] / 2;
    const int tot = E + N;

    init_kernel<<<(MAXG * HID > N ? MAXG * HID : N + 255) / 256 + 1, 256>>>(pool, N);
    prepW_kernel<<<(NKB * 8 * 128 + 255) / 256, 256>>>(W);
    gemm_tf32_kernel<<<(N + 127) / 128, 256>>>(x, N);
    attdot_kernel<<<(N * 32 + 255) / 256, 256>>>(att_src, att_dst, N);
    // CSR build
    count_kernel<<<(E + 255) / 256, 256>>>(ei, E);
    scan_kernel<<<1, SCAN_T>>>(N);
    scatter_kernel<<<(tot + 255) / 256, 256>>>(ei, E, N);
    // fused softmax + aggregate + relu + pool
    gat_kernel<<<(N * 32 + 255) / 256, 256>>>(bias, batch, pool, N);
}

// round 4
// speedup vs baseline: 2.2037x; 1.2878x over previous
#include <cuda_runtime.h>
#include <math.h>
#include <stdint.h>

#define MAXN     50000
#define MAXE     1600000
#define IN_DIM   1024
#define HID      128
#define MAXG     64
#define MAXETOT  (MAXE + MAXN)
#define NKB      (IN_DIM / 16)   // 64 k-blocks of 16

// GEMM pipeline config
#define S_STAGES  4
#define AS_STRIDE 20                         // floats per A row (16 used, pad to 20)
#define AS_FLOATS (128 * AS_STRIDE)          // per stage
#define AS_BYTES  (AS_FLOATS * 4)
#define BS_F2     (8 * 132)                  // per stage (slot-major, padded)
#define BS_BYTES  (BS_F2 * 8)
#define GEMM_SMEM (S_STAGES * (AS_BYTES + BS_BYTES))

// ---------------- device scratch (static; no allocations) ----------------
__device__ float g_h[(size_t)MAXN * HID];     // h = x @ W
__device__ float g_e[MAXETOT];                // per-edge e then p, CSR order
__device__ float g_asrc[MAXN];
__device__ float g_adst[MAXN];
__device__ int   g_cnt[MAXN];                 // per-dst in-degree (zeroed by scan1 each run)
__device__ int   g_off[MAXN + 1];             // CSR offsets
__device__ int   g_cur[MAXN];                 // scatter cursors
__device__ int   g_csr_src[MAXETOT];          // src ids grouped by dst
__device__ int   g_bsum[256];                 // scan block sums
__device__ int   g_bpre[256];                 // scan block prefixes
__device__ float2 g_Wp[NKB * 8 * 128];        // W permuted tf32 pairs

// ---------------- helpers ----------------
__device__ __forceinline__ float tf32r(float x) {
    unsigned int t;
    asm("cvt.rna.tf32.f32 %0, %1;" : "=r"(t) : "f"(x));
    return __uint_as_float(t);
}

// ---------------- kernels ----------------

// combo: pool=0, W permute, per-dst edge count (g_cnt starts zeroed: .bss at
// load, and scan1 re-zeroes it each run).
__global__ void combo_kernel(const float* __restrict__ W,
                             const int* __restrict__ ei, int E, float* pool) {
    int i = blockIdx.x * blockDim.x + threadIdx.x;
    if (i < MAXG * HID) pool[i] = 0.f;
    if (i < NKB * 8 * 128) {
        int n = i & 127;
        int s = (i >> 7) & 7;
        int kb = i >> 10;
        int ks = ((s >> 2) << 3) + (s & 3);
        int k0 = kb * 16 + ks;
        g_Wp[i] = make_float2(tf32r(W[(size_t)k0 * HID + n]),
                              tf32r(W[(size_t)(k0 + 4) * HID + n]));
    }
    if (i < E) atomicAdd(&g_cnt[ei[E + i]], 1);
}

// TF32 tensor-core GEMM: g_h[M,128] = A[M,1024] @ W[1024,128]
// BM=128, BN=128, BK=16, 256 threads, 8 warps (4m x 2n), 4-stage cp.async.
__global__ __launch_bounds__(256) void gemm_tf32_kernel(const float* __restrict__ A,
                                                        int M) {
    extern __shared__ float smem[];
    float2* BsAll = (float2*)(smem + S_STAGES * AS_FLOATS);

    const int tid  = threadIdx.x;
    const int lane = tid & 31;
    const int warp = tid >> 5;
    const int gid  = lane >> 2;
    const int tig  = lane & 3;
    const int wm   = (warp & 3) * 32;
    const int wn   = (warp >> 2) * 64;
    const int block_row = blockIdx.x * 128;

    uint32_t sbase = (uint32_t)__cvta_generic_to_shared(smem);

    // A load: thread covers 2 16B chunks; chunk c: row=c>>2, quad=c&3
    const int c0 = tid * 2;
    const int arow0 = c0 >> 2,       aq0 = c0 & 3;
    const int arow1 = (c0 + 1) >> 2, aq1 = (c0 + 1) & 3;
    const float* aptr0 = A + (size_t)(block_row + arow0) * IN_DIM + aq0 * 4;
    const float* aptr1 = A + (size_t)(block_row + arow1) * IN_DIM + aq1 * 4;
    const int av0 = (block_row + arow0) < M ? 16 : 0;   // src-size (0 = zfill)
    const int av1 = (block_row + arow1) < M ? 16 : 0;
    const uint32_t a_dst0 = sbase + (arow0 * AS_STRIDE + aq0 * 4) * 4;
    const uint32_t a_dst1 = sbase + (arow1 * AS_STRIDE + aq1 * 4) * 4;
    // B load: thread covers f2 indices tid*4 .. tid*4+3 (two 16B chunks)
    const uint32_t b_dst = sbase + S_STAGES * AS_BYTES +
                           ((tid >> 5) * 132 + (tid & 31) * 4) * 8;

#define GEMM_ISSUE(kb_, s_) do {                                              \
    const float* a0s_ = aptr0 + (kb_) * 16;                                   \
    const float* a1s_ = aptr1 + (kb_) * 16;                                   \
    uint32_t ad0_ = a_dst0 + (s_) * AS_BYTES;                                 \
    uint32_t ad1_ = a_dst1 + (s_) * AS_BYTES;                                 \
    asm volatile("cp.async.cg.shared.global [%0], [%1], 16, %2;"              \
                 :: "r"(ad0_), "l"(a0s_), "r"(av0));                          \
    asm volatile("cp.async.cg.shared.global [%0], [%1], 16, %2;"              \
                 :: "r"(ad1_), "l"(a1s_), "r"(av1));                          \
    const float2* bsrc_ = g_Wp + (size_t)(kb_) * 1024 + tid * 4;              \
    uint32_t bd_ = b_dst + (s_) * BS_BYTES;                                   \
    asm volatile("cp.async.cg.shared.global [%0], [%1], 16;"                  \
                 :: "r"(bd_), "l"(bsrc_));                                    \
    asm volatile("cp.async.cg.shared.global [%0], [%1], 16;"                  \
                 :: "r"(bd_ + 16), "l"(bsrc_ + 2));                           \
} while (0)

    float acc[2][8][4];
#pragma unroll
    for (int mt = 0; mt < 2; mt++)
#pragma unroll
        for (int nt = 0; nt < 8; nt++)
#pragma unroll
            for (int i = 0; i < 4; i++) acc[mt][nt][i] = 0.f;

    // prologue: stages 0..S-2 in flight
#pragma unroll
    for (int s = 0; s < S_STAGES - 1; s++) {
        GEMM_ISSUE(s, s);
        asm volatile("cp.async.commit_group;");
    }

#pragma unroll 1
    for (int kb = 0; kb < NKB; kb++) {
        asm volatile("cp.async.wait_group %0;" :: "n"(S_STAGES - 2));
        __syncthreads();

        int nk = kb + S_STAGES - 1;
        if (nk < NKB) GEMM_ISSUE(nk, nk % S_STAGES);
        asm volatile("cp.async.commit_group;");

        const int buf = kb % S_STAGES;
        const float* As_ = smem + buf * AS_FLOATS;
        const float2* Bs_ = BsAll + buf * BS_F2;

#pragma unroll
        for (int ks = 0; ks < 2; ks++) {
            float a0[2], a1[2], a2[2], a3[2];
#pragma unroll
            for (int mt = 0; mt < 2; mt++) {
                int r0 = wm + mt * 16 + gid;
                a0[mt] = As_[r0 * AS_STRIDE + ks * 8 + tig];
                a1[mt] = As_[(r0 + 8) * AS_STRIDE + ks * 8 + tig];
                a2[mt] = As_[r0 * AS_STRIDE + ks * 8 + tig + 4];
                a3[mt] = As_[(r0 + 8) * AS_STRIDE + ks * 8 + tig + 4];
            }
            float2 bfr[8];
#pragma unroll
            for (int nt = 0; nt < 8; nt++)
                bfr[nt] = Bs_[(ks * 4 + tig) * 132 + wn + nt * 8 + gid];
#pragma unroll
            for (int mt = 0; mt < 2; mt++)
#pragma unroll
                for (int nt = 0; nt < 8; nt++) {
                    asm("mma.sync.aligned.m16n8k8.row.col.f32.tf32.tf32.f32 "
                        "{%0,%1,%2,%3}, {%4,%5,%6,%7}, {%8,%9}, {%0,%1,%2,%3};"
                        : "+f"(acc[mt][nt][0]), "+f"(acc[mt][nt][1]),
                          "+f"(acc[mt][nt][2]), "+f"(acc[mt][nt][3])
                        : "r"(__float_as_uint(a0[mt])),
                          "r"(__float_as_uint(a1[mt])),
                          "r"(__float_as_uint(a2[mt])),
                          "r"(__float_as_uint(a3[mt])),
                          "r"(__float_as_uint(bfr[nt].x)),
                          "r"(__float_as_uint(bfr[nt].y)));
                }
        }
    }
#undef GEMM_ISSUE

#pragma unroll
    for (int mt = 0; mt < 2; mt++) {
        int row0 = block_row + wm + mt * 16 + gid;
#pragma unroll
        for (int nt = 0; nt < 8; nt++) {
            int col = wn + nt * 8 + tig * 2;
            if (row0 < M)
                *(float2*)&g_h[(size_t)row0 * HID + col] =
                    make_float2(acc[mt][nt][0], acc[mt][nt][1]);
            if (row0 + 8 < M)
                *(float2*)&g_h[(size_t)(row0 + 8) * HID + col] =
                    make_float2(acc[mt][nt][2], acc[mt][nt][3]);
        }
    }
}

// a_src[n] = h[n]·att_src ; a_dst[n] = h[n]·att_dst (one warp per node)
__global__ void attdot_kernel(const float* __restrict__ att_src,
                              const float* __restrict__ att_dst, int N) {
    int warp = (blockIdx.x * blockDim.x + threadIdx.x) >> 5;
    int lane = threadIdx.x & 31;
    if (warp >= N) return;
    float4 hv = ((const float4*)g_h)[(size_t)warp * 32 + lane];
    float4 s4 = ((const float4*)att_src)[lane];
    float4 d4 = ((const float4*)att_dst)[lane];
    float ps = hv.x * s4.x + hv.y * s4.y + hv.z * s4.z + hv.w * s4.w;
    float pd = hv.x * d4.x + hv.y * d4.y + hv.z * d4.z + hv.w * d4.w;
#pragma unroll
    for (int o = 16; o; o >>= 1) {
        ps += __shfl_xor_sync(0xffffffffu, ps, o);
        pd += __shfl_xor_sync(0xffffffffu, pd, o);
    }
    if (lane == 0) { g_asrc[warp] = ps; g_adst[warp] = pd; }
}

// ---- parallel exclusive scan of (g_cnt[i]+1) into g_off / g_cur ----

// scan1: per-block (256 nodes) local exclusive scan; writes block sums.
// Also resets g_cnt to 0 for the next graph replay.
__global__ __launch_bounds__(256) void scan1_kernel(int N) {
    __shared__ int ws[8];
    int t = threadIdx.x, b = blockIdx.x;
    int i = b * 256 + t;
    int c = 0;
    if (i < N) { c = g_cnt[i] + 1; g_cnt[i] = 0; }   // +1 = self loop
    int lane = t & 31, w = t >> 5;
    int v = c;
#pragma unroll
    for (int o = 1; o < 32; o <<= 1) {
        int u = __shfl_up_sync(0xffffffffu, v, o);
        if (lane >= o) v += u;
    }
    if (lane == 31) ws[w] = v;
    __syncthreads();
    if (w == 0) {
        int x = (lane < 8) ? ws[lane] : 0;
#pragma unroll
        for (int o = 1; o < 8; o <<= 1) {
            int u = __shfl_up_sync(0xffffffffu, x, o);
            if (lane >= o) x += u;
        }
        if (lane < 8) ws[lane] = x;
    }
    __syncthreads();
    int excl = v - c + (w > 0 ? ws[w - 1] : 0);
    if (i < N) g_off[i] = excl;
    if (t == 255) g_bsum[b] = excl + c;
}

// scan2: exclusive scan of block sums (single block, <=256 blocks)
__global__ __launch_bounds__(256) void scan2_kernel(int nb, int N) {
    __shared__ int ws[8];
    int t = threadIdx.x;
    int c = (t < nb) ? g_bsum[t] : 0;
    int lane = t & 31, w = t >> 5;
    int v = c;
#pragma unroll
    for (int o = 1; o < 32; o <<= 1) {
        int u = __shfl_up_sync(0xffffffffu, v, o);
        if (lane >= o) v += u;
    }
    if (lane == 31) ws[w] = v;
    __syncthreads();
    if (w == 0) {
        int x = (lane < 8) ? ws[lane] : 0;
#pragma unroll
        for (int o = 1; o < 8; o <<= 1) {
            int u = __shfl_up_sync(0xffffffffu, x, o);
            if (lane >= o) x += u;
        }
        if (lane < 8) ws[lane] = x;
    }
    __syncthreads();
    int incl = v + (w > 0 ? ws[w - 1] : 0);
    if (t < nb) g_bpre[t] = incl - c;
    if (t == 255) g_off[N] = incl;   // grand total
}

// scan3: add block prefixes; init cursors
__global__ void scan3_kernel(int N) {
    int i = blockIdx.x * blockDim.x + threadIdx.x;
    if (i >= N) return;
    int o = g_off[i] + g_bpre[blockIdx.x];
    g_off[i] = o;
    g_cur[i] = o;
}

// scatter edges (and self loops) into CSR order (order within dst irrelevant)
__global__ void scatter_kernel(const int* __restrict__ ei, int E, int N) {
    int i = blockIdx.x * blockDim.x + threadIdx.x;
    int tot = E + N;
    if (i >= tot) return;
    int s, d;
    if (i < E) { s = ei[i]; d = ei[E + i]; }
    else       { s = d = i - E; }
    int pos = atomicAdd(&g_cur[d], 1);
    g_csr_src[pos] = s;
}

// fused GAT: warp per dst node. softmax over incoming edges, weighted
// aggregation, bias+relu, global max pool — all in one pass.
__global__ __launch_bounds__(256) void gat_kernel(const float* __restrict__ bias,
                                                  const int* __restrict__ batch,
                                                  float* pool, int N) {
    int node = (blockIdx.x * blockDim.x + threadIdx.x) >> 5;
    int lane = threadIdx.x & 31;
    if (node >= N) return;

    int base = g_off[node];
    int deg  = g_off[node + 1] - base;
    float adst = g_adst[node];

    // loop 1: e = leaky_relu(a_src[s] + a_dst[d]); warp max
    float m = -INFINITY;
    for (int j = lane; j < deg; j += 32) {
        int s = g_csr_src[base + j];
        float e = g_asrc[s] + adst;
        e = e > 0.f ? e : 0.2f * e;
        g_e[base + j] = e;
        m = fmaxf(m, e);
    }
#pragma unroll
    for (int o = 16; o; o >>= 1)
        m = fmaxf(m, __shfl_xor_sync(0xffffffffu, m, o));

    // loop 2: p = exp(e - m); warp sum
    float den = 0.f;
    for (int j = lane; j < deg; j += 32) {
        float p = __expf(g_e[base + j] - m);
        g_e[base + j] = p;
        den += p;
    }
#pragma unroll
    for (int o = 16; o; o >>= 1)
        den += __shfl_xor_sync(0xffffffffu, den, o);

    // loop 3: acc = sum p * h[s]; dual accumulators, 2 gathers in flight
    float4 acc0 = make_float4(0.f, 0.f, 0.f, 0.f);
    float4 acc1 = make_float4(0.f, 0.f, 0.f, 0.f);
    int j = 0;
    for (; j + 2 <= deg; j += 2) {
        float p0 = g_e[base + j];
        float p1 = g_e[base + j + 1];
        int s0 = g_csr_src[base + j];
        int s1 = g_csr_src[base + j + 1];
        float4 h0 = ((const float4*)g_h)[(size_t)s0 * 32 + lane];
        float4 h1 = ((const float4*)g_h)[(size_t)s1 * 32 + lane];
        acc0.x = fmaf(p0, h0.x, acc0.x);
        acc0.y = fmaf(p0, h0.y, acc0.y);
        acc0.z = fmaf(p0, h0.z, acc0.z);
        acc0.w = fmaf(p0, h0.w, acc0.w);
        acc1.x = fmaf(p1, h1.x, acc1.x);
        acc1.y = fmaf(p1, h1.y, acc1.y);
        acc1.z = fmaf(p1, h1.z, acc1.z);
        acc1.w = fmaf(p1, h1.w, acc1.w);
    }
    if (j < deg) {
        float p0 = g_e[base + j];
        int s0 = g_csr_src[base + j];
        float4 h0 = ((const float4*)g_h)[(size_t)s0 * 32 + lane];
        acc0.x = fmaf(p0, h0.x, acc0.x);
        acc0.y = fmaf(p0, h0.y, acc0.y);
        acc0.z = fmaf(p0, h0.z, acc0.z);
        acc0.w = fmaf(p0, h0.w, acc0.w);
    }

    float inv = 1.f / den;
    float4 b = ((const float4*)bias)[lane];
    float4 v;
    v.x = fmaxf((acc0.x + acc1.x) * inv + b.x, 0.f);
    v.y = fmaxf((acc0.y + acc1.y) * inv + b.y, 0.f);
    v.z = fmaxf((acc0.z + acc1.z) * inv + b.z, 0.f);
    v.w = fmaxf((acc0.w + acc1.w) * inv + b.w, 0.f);

    int g = batch[node];
    int* p = (int*)(pool + (size_t)g * HID + lane * 4);
    // values >= 0 so signed-int compare is order-preserving
    atomicMax(p + 0, __float_as_int(v.x));
    atomicMax(p + 1, __float_as_int(v.y));
    atomicMax(p + 2, __float_as_int(v.z));
    atomicMax(p + 3, __float_as_int(v.w));
}

// ---------------- launch ----------------
extern "C" void kernel_launch(void* const* d_in, const int* in_sizes, int n_in,
                              void* d_out, int out_size) {
    const float* x       = (const float*)d_in[0];   // [N, 1024]
    const float* W       = (const float*)d_in[1];   // [1024, 128]
    const float* att_src = (const float*)d_in[2];   // [128]
    const float* att_dst = (const float*)d_in[3];   // [128]
    const float* bias    = (const float*)d_in[4];   // [128]
    const int*   ei      = (const int*)d_in[5];     // [2, E]
    const int*   batch   = (const int*)d_in[6];     // [N]
    float* pool = (float*)d_out;                    // [G, 128]

    const int N = in_sizes[0] / IN_DIM;
    const int E = in_sizes[5] / 2;
    const int tot = E + N;
    const int nb = (N + 255) / 256;

    cudaFuncSetAttribute(gemm_tf32_kernel,
                         cudaFuncAttributeMaxDynamicSharedMemorySize, GEMM_SMEM);

    // pool init + W permute + edge count (independent work, one launch)
    combo_kernel<<<(E + 255) / 256, 256>>>(W, ei, E, pool);
    // GEMM h = x @ W (tf32 tensor cores, cp.async pipeline)
    gemm_tf32_kernel<<<(N + 127) / 128, 256, GEMM_SMEM>>>(x, N);
    // a_src / a_dst
    attdot_kernel<<<(N * 32 + 255) / 256, 256>>>(att_src, att_dst, N);
    // CSR offsets (parallel scan) + scatter
    scan1_kernel<<<nb, 256>>>(N);
    scan2_kernel<<<1, 256>>>(nb, N);
    scan3_kernel<<<nb, 256>>>(N);
    scatter_kernel<<<(tot + 255) / 256, 256>>>(ei, E, N);
    // fused softmax + aggregate + relu + pool
    gat_kernel<<<(N * 32 + 255) / 256, 256>>>(bias, batch, pool, N);
}

// round 5
// speedup vs baseline: 2.3731x; 1.0769x over previous
#include <cuda_runtime.h>
#include <cuda_fp16.h>
#include <math.h>
#include <stdint.h>

#define MAXN     50000
#define MAXE     1600000
#define IN_DIM   1024
#define HID      128
#define MAXG     64
#define MAXETOT  (MAXE + MAXN)
#define NKB      (IN_DIM / 16)   // 64 k-blocks of 16

// GEMM pipeline config: 128 threads, 4 warps (2m x 2n), warp tile 64x64
#define S_STAGES  4
#define AS_STRIDE 20                         // floats per A row (16 used, pad to 20)
#define AS_FLOATS (128 * AS_STRIDE)          // per stage
#define AS_BYTES  (AS_FLOATS * 4)
#define BS_F2     (8 * 132)                  // per stage (slot-major, padded)
#define BS_BYTES  (BS_F2 * 8)
#define GEMM_SMEM (S_STAGES * (AS_BYTES + BS_BYTES))

// ---------------- device scratch (static; no allocations) ----------------
__device__ float  g_h[(size_t)MAXN * HID];    // h = x @ W (fp32, for reference path)
__device__ __half g_hh[(size_t)MAXN * HID];   // h in fp16 (gather copy)
__device__ float  g_e[MAXETOT];               // per-edge p, CSR order
__device__ float  g_asrc[MAXN];
__device__ float  g_adst[MAXN];
__device__ int    g_cnt[MAXN];                // per-dst in-degree (re-zeroed by scan1)
__device__ int    g_off[MAXN + 1];            // CSR offsets
__device__ int    g_cur[MAXN];                // scatter cursors
__device__ int    g_csr_src[MAXETOT];         // src ids grouped by dst
__device__ int    g_bsum[256];                // scan block sums
__device__ int    g_bpre[256];                // scan block prefixes
__device__ float2 g_Wp[NKB * 8 * 128];        // W permuted tf32 pairs

// ---------------- helpers ----------------
__device__ __forceinline__ float tf32r(float x) {
    unsigned int t;
    asm("cvt.rna.tf32.f32 %0, %1;" : "=r"(t) : "f"(x));
    return __uint_as_float(t);
}

// ---------------- kernels ----------------

// combo: pool=0, W permute, per-dst edge count.
__global__ void combo_kernel(const float* __restrict__ W,
                             const int* __restrict__ ei, int E, float* pool) {
    int i = blockIdx.x * blockDim.x + threadIdx.x;
    if (i < MAXG * HID) pool[i] = 0.f;
    if (i < NKB * 8 * 128) {
        int n = i & 127;
        int s = (i >> 7) & 7;
        int kb = i >> 10;
        int ks = ((s >> 2) << 3) + (s & 3);
        int k0 = kb * 16 + ks;
        g_Wp[i] = make_float2(tf32r(W[(size_t)k0 * HID + n]),
                              tf32r(W[(size_t)(k0 + 4) * HID + n]));
    }
    if (i < E) atomicAdd(&g_cnt[ei[E + i]], 1);
}

// TF32 tensor-core GEMM with fused attdot epilogue.
// g_h/g_hh[M,128] = A[M,1024] @ W ; g_asrc/g_adst = h . att_{src,dst}
// 128 threads, 4 warps (warp&1 = m-half, warp>>1 = n-half), warp tile 64x64.
__global__ __launch_bounds__(128, 2) void gemm_tf32_kernel(
        const float* __restrict__ A,
        const float* __restrict__ att_src,
        const float* __restrict__ att_dst, int M) {
    extern __shared__ float smem[];
    float2* BsAll = (float2*)(smem + S_STAGES * AS_FLOATS);

    const int tid  = threadIdx.x;
    const int lane = tid & 31;
    const int warp = tid >> 5;
    const int gid  = lane >> 2;   // 0..7
    const int tig  = lane & 3;    // 0..3
    const int wm   = (warp & 1) * 64;
    const int wn   = (warp >> 1) * 64;
    const int block_row = blockIdx.x * 128;

    uint32_t sbase = (uint32_t)__cvta_generic_to_shared(smem);

    // A load: 4 instrs, instr i: row = i*32 + (t>>2), quad = t&3 (64B/row coalesced)
    const int lrow = tid >> 2;        // 0..31
    const int lq   = tid & 3;         // 0..3
    // B load: 4 instrs, instr j: chunk = j*128 + t  (fully coalesced 2KB)
    // chunk c -> src f2 idx 2c: slot = (2c)>>7, n = (2c)&127

#define GEMM_ISSUE(kb_, s_) do {                                                \
    _Pragma("unroll")                                                           \
    for (int ii = 0; ii < 4; ii++) {                                            \
        int row_ = ii * 32 + lrow;                                              \
        int gr_ = block_row + row_;                                             \
        const float* asrc_ = A + (size_t)gr_ * IN_DIM + (kb_) * 16 + lq * 4;    \
        int sz_ = (gr_ < M) ? 16 : 0;                                           \
        uint32_t ad_ = sbase + (s_) * AS_BYTES + (row_ * AS_STRIDE + lq * 4) * 4; \
        asm volatile("cp.async.cg.shared.global [%0], [%1], 16, %2;"            \
                     :: "r"(ad_), "l"(asrc_), "r"(sz_));                        \
    }                                                                           \
    _Pragma("unroll")                                                           \
    for (int jj = 0; jj < 4; jj++) {                                            \
        int f2i_ = 2 * (jj * 128 + tid);                                        \
        int slot_ = f2i_ >> 7, nn_ = f2i_ & 127;                                \
        const float2* bsrc_ = g_Wp + (size_t)(kb_) * 1024 + f2i_;               \
        uint32_t bd_ = sbase + S_STAGES * AS_BYTES + (s_) * BS_BYTES +          \
                       (slot_ * 132 + nn_) * 8;                                 \
        asm volatile("cp.async.cg.shared.global [%0], [%1], 16;"                \
                     :: "r"(bd_), "l"(bsrc_));                                  \
    }                                                                           \
} while (0)

    float acc[4][8][4];
#pragma unroll
    for (int mt = 0; mt < 4; mt++)
#pragma unroll
        for (int nt = 0; nt < 8; nt++)
#pragma unroll
            for (int i = 0; i < 4; i++) acc[mt][nt][i] = 0.f;

    // prologue
#pragma unroll
    for (int s = 0; s < S_STAGES - 1; s++) {
        GEMM_ISSUE(s, s);
        asm volatile("cp.async.commit_group;");
    }

#pragma unroll 1
    for (int kb = 0; kb < NKB; kb++) {
        asm volatile("cp.async.wait_group %0;" :: "n"(S_STAGES - 2));
        __syncthreads();

        int nk = kb + S_STAGES - 1;
        if (nk < NKB) GEMM_ISSUE(nk, nk % S_STAGES);
        asm volatile("cp.async.commit_group;");

        const int buf = kb % S_STAGES;
        const float* As_ = smem + buf * AS_FLOATS;
        const float2* Bs_ = BsAll + buf * BS_F2;

#pragma unroll
        for (int ks = 0; ks < 2; ks++) {
            float a0[4], a1[4], a2[4], a3[4];
#pragma unroll
            for (int mt = 0; mt < 4; mt++) {
                int r0 = wm + mt * 16 + gid;
                a0[mt] = As_[r0 * AS_STRIDE + ks * 8 + tig];
                a1[mt] = As_[(r0 + 8) * AS_STRIDE + ks * 8 + tig];
                a2[mt] = As_[r0 * AS_STRIDE + ks * 8 + tig + 4];
                a3[mt] = As_[(r0 + 8) * AS_STRIDE + ks * 8 + tig + 4];
            }
            float2 bfr[8];
#pragma unroll
            for (int nt = 0; nt < 8; nt++)
                bfr[nt] = Bs_[(ks * 4 + tig) * 132 + wn + nt * 8 + gid];
#pragma unroll
            for (int mt = 0; mt < 4; mt++)
#pragma unroll
                for (int nt = 0; nt < 8; nt++) {
                    asm("mma.sync.aligned.m16n8k8.row.col.f32.tf32.tf32.f32 "
                        "{%0,%1,%2,%3}, {%4,%5,%6,%7}, {%8,%9}, {%0,%1,%2,%3};"
                        : "+f"(acc[mt][nt][0]), "+f"(acc[mt][nt][1]),
                          "+f"(acc[mt][nt][2]), "+f"(acc[mt][nt][3])
                        : "r"(__float_as_uint(a0[mt])),
                          "r"(__float_as_uint(a1[mt])),
                          "r"(__float_as_uint(a2[mt])),
                          "r"(__float_as_uint(a3[mt])),
                          "r"(__float_as_uint(bfr[nt].x)),
                          "r"(__float_as_uint(bfr[nt].y)));
                }
        }
    }
#undef GEMM_ISSUE

    // ---- epilogue: write h (fp32 + fp16), fused attdot ----
    float psrc[4][2], pdst[4][2];
#pragma unroll
    for (int mt = 0; mt < 4; mt++) {
        psrc[mt][0] = psrc[mt][1] = 0.f;
        pdst[mt][0] = pdst[mt][1] = 0.f;
    }

#pragma unroll
    for (int mt = 0; mt < 4; mt++) {
        int row0 = block_row + wm + mt * 16 + gid;
#pragma unroll
        for (int nt = 0; nt < 8; nt++) {
            int col = wn + nt * 8 + tig * 2;
            float s0 = __ldg(att_src + col), s1 = __ldg(att_src + col + 1);
            float d0 = __ldg(att_dst + col), d1 = __ldg(att_dst + col + 1);
            psrc[mt][0] += acc[mt][nt][0] * s0 + acc[mt][nt][1] * s1;
            pdst[mt][0] += acc[mt][nt][0] * d0 + acc[mt][nt][1] * d1;
            psrc[mt][1] += acc[mt][nt][2] * s0 + acc[mt][nt][3] * s1;
            pdst[mt][1] += acc[mt][nt][2] * d0 + acc[mt][nt][3] * d1;
            if (row0 < M) {
                float2 v = make_float2(acc[mt][nt][0], acc[mt][nt][1]);
                *(float2*)&g_h[(size_t)row0 * HID + col] = v;
                *(__half2*)&g_hh[(size_t)row0 * HID + col] = __float22half2_rn(v);
            }
            if (row0 + 8 < M) {
                float2 v = make_float2(acc[mt][nt][2], acc[mt][nt][3]);
                *(float2*)&g_h[(size_t)(row0 + 8) * HID + col] = v;
                *(__half2*)&g_hh[(size_t)(row0 + 8) * HID + col] = __float22half2_rn(v);
            }
        }
    }

    // reduce over quad (tig lanes)
#pragma unroll
    for (int mt = 0; mt < 4; mt++)
#pragma unroll
        for (int hf = 0; hf < 2; hf++) {
            psrc[mt][hf] += __shfl_xor_sync(0xffffffffu, psrc[mt][hf], 1);
            psrc[mt][hf] += __shfl_xor_sync(0xffffffffu, psrc[mt][hf], 2);
            pdst[mt][hf] += __shfl_xor_sync(0xffffffffu, pdst[mt][hf], 1);
            pdst[mt][hf] += __shfl_xor_sync(0xffffffffu, pdst[mt][hf], 2);
        }

    __syncthreads();   // pipeline smem no longer needed; reuse for reduction
    float* rs = smem;          // [128][2]
    float* rd = smem + 256;    // [128][2]
    int nh = warp >> 1;
    if (tig == 0) {
#pragma unroll
        for (int mt = 0; mt < 4; mt++) {
#pragma unroll
            for (int hf = 0; hf < 2; hf++) {
                int rl = wm + mt * 16 + gid + hf * 8;
                rs[rl * 2 + nh] = psrc[mt][hf];
                rd[rl * 2 + nh] = pdst[mt][hf];
            }
        }
    }
    __syncthreads();
    int r = block_row + tid;
    if (r < M) {
        g_asrc[r] = rs[tid * 2] + rs[tid * 2 + 1];
        g_adst[r] = rd[tid * 2] + rd[tid * 2 + 1];
    }
}

// ---- parallel exclusive scan of (g_cnt[i]+1) into g_off / g_cur ----
__global__ __launch_bounds__(256) void scan1_kernel(int N) {
    __shared__ int ws[8];
    int t = threadIdx.x, b = blockIdx.x;
    int i = b * 256 + t;
    int c = 0;
    if (i < N) { c = g_cnt[i] + 1; g_cnt[i] = 0; }   // +1 = self loop
    int lane = t & 31, w = t >> 5;
    int v = c;
#pragma unroll
    for (int o = 1; o < 32; o <<= 1) {
        int u = __shfl_up_sync(0xffffffffu, v, o);
        if (lane >= o) v += u;
    }
    if (lane == 31) ws[w] = v;
    __syncthreads();
    if (w == 0) {
        int x = (lane < 8) ? ws[lane] : 0;
#pragma unroll
        for (int o = 1; o < 8; o <<= 1) {
            int u = __shfl_up_sync(0xffffffffu, x, o);
            if (lane >= o) x += u;
        }
        if (lane < 8) ws[lane] = x;
    }
    __syncthreads();
    int excl = v - c + (w > 0 ? ws[w - 1] : 0);
    if (i < N) g_off[i] = excl;
    if (t == 255) g_bsum[b] = excl + c;
}

__global__ __launch_bounds__(256) void scan2_kernel(int nb, int N) {
    __shared__ int ws[8];
    int t = threadIdx.x;
    int c = (t < nb) ? g_bsum[t] : 0;
    int lane = t & 31, w = t >> 5;
    int v = c;
#pragma unroll
    for (int o = 1; o < 32; o <<= 1) {
        int u = __shfl_up_sync(0xffffffffu, v, o);
        if (lane >= o) v += u;
    }
    if (lane == 31) ws[w] = v;
    __syncthreads();
    if (w == 0) {
        int x = (lane < 8) ? ws[lane] : 0;
#pragma unroll
        for (int o = 1; o < 8; o <<= 1) {
            int u = __shfl_up_sync(0xffffffffu, x, o);
            if (lane >= o) x += u;
        }
        if (lane < 8) ws[lane] = x;
    }
    __syncthreads();
    int incl = v + (w > 0 ? ws[w - 1] : 0);
    if (t < nb) g_bpre[t] = incl - c;
    if (t == 255) g_off[N] = incl;
}

__global__ void scan3_kernel(int N) {
    int i = blockIdx.x * blockDim.x + threadIdx.x;
    if (i >= N) return;
    int o = g_off[i] + g_bpre[blockIdx.x];
    g_off[i] = o;
    g_cur[i] = o;
}

// scatter edges (and self loops) into CSR order
__global__ void scatter_kernel(const int* __restrict__ ei, int E, int N) {
    int i = blockIdx.x * blockDim.x + threadIdx.x;
    int tot = E + N;
    if (i >= tot) return;
    int s, d;
    if (i < E) { s = ei[i]; d = ei[E + i]; }
    else       { s = d = i - E; }
    int pos = atomicAdd(&g_cur[d], 1);
    g_csr_src[pos] = s;
}

// fused GAT: warp per dst node. p=exp(leakyrelu(e)) (no max shift — e bounded),
// weighted aggregation from fp16 h, bias+relu, global max pool.
__global__ __launch_bounds__(256) void gat_kernel(const float* __restrict__ bias,
                                                  const int* __restrict__ batch,
                                                  float* pool, int N) {
    int node = (blockIdx.x * blockDim.x + threadIdx.x) >> 5;
    int lane = threadIdx.x & 31;
    if (node >= N) return;

    int base = g_off[node];
    int deg  = g_off[node + 1] - base;
    float adst = g_adst[node];

    // merged pass: p = exp(leaky_relu(a_src[s] + adst)); warp sum
    float den = 0.f;
    for (int j = lane; j < deg; j += 32) {
        int s = g_csr_src[base + j];
        float e = g_asrc[s] + adst;
        e = e > 0.f ? e : 0.2f * e;
        float p = __expf(e);
        g_e[base + j] = p;
        den += p;
    }
#pragma unroll
    for (int o = 16; o; o >>= 1)
        den += __shfl_xor_sync(0xffffffffu, den, o);

    // aggregation: acc = sum p * h[s] (fp16 gather, unroll 4)
    const uint2* hh = (const uint2*)g_hh;   // 32 uint2 per row
    float4 A0 = make_float4(0.f, 0.f, 0.f, 0.f);
    float4 A1 = make_float4(0.f, 0.f, 0.f, 0.f);
    int j = 0;
    for (; j + 4 <= deg; j += 4) {
        float p0 = g_e[base + j],     p1 = g_e[base + j + 1];
        float p2 = g_e[base + j + 2], p3 = g_e[base + j + 3];
        int s0 = g_csr_src[base + j],     s1 = g_csr_src[base + j + 1];
        int s2 = g_csr_src[base + j + 2], s3 = g_csr_src[base + j + 3];
        uint2 v0 = hh[(size_t)s0 * 32 + lane];
        uint2 v1 = hh[(size_t)s1 * 32 + lane];
        uint2 v2 = hh[(size_t)s2 * 32 + lane];
        uint2 v3 = hh[(size_t)s3 * 32 + lane];
        float2 f;
        f = __half22float2(*(__half2*)&v0.x); A0.x = fmaf(p0, f.x, A0.x); A0.y = fmaf(p0, f.y, A0.y);
        f = __half22float2(*(__half2*)&v0.y); A0.z = fmaf(p0, f.x, A0.z); A0.w = fmaf(p0, f.y, A0.w);
        f = __half22float2(*(__half2*)&v1.x); A1.x = fmaf(p1, f.x, A1.x); A1.y = fmaf(p1, f.y, A1.y);
        f = __half22float2(*(__half2*)&v1.y); A1.z = fmaf(p1, f.x, A1.z); A1.w = fmaf(p1, f.y, A1.w);
        f = __half22float2(*(__half2*)&v2.x); A0.x = fmaf(p2, f.x, A0.x); A0.y = fmaf(p2, f.y, A0.y);
        f = __half22float2(*(__half2*)&v2.y); A0.z = fmaf(p2, f.x, A0.z); A0.w = fmaf(p2, f.y, A0.w);
        f = __half22float2(*(__half2*)&v3.x); A1.x = fmaf(p3, f.x, A1.x); A1.y = fmaf(p3, f.y, A1.y);
        f = __half22float2(*(__half2*)&v3.y); A1.z = fmaf(p3, f.x, A1.z); A1.w = fmaf(p3, f.y, A1.w);
    }
    for (; j < deg; j++) {
        float p0 = g_e[base + j];
        int s0 = g_csr_src[base + j];
        uint2 v0 = hh[(size_t)s0 * 32 + lane];
        float2 f;
        f = __half22float2(*(__half2*)&v0.x); A0.x = fmaf(p0, f.x, A0.x); A0.y = fmaf(p0, f.y, A0.y);
        f = __half22float2(*(__half2*)&v0.y); A0.z = fmaf(p0, f.x, A0.z); A0.w = fmaf(p0, f.y, A0.w);
    }

    float inv = 1.f / den;
    float4 b = ((const float4*)bias)[lane];
    float4 v;
    v.x = fmaxf((A0.x + A1.x) * inv + b.x, 0.f);
    v.y = fmaxf((A0.y + A1.y) * inv + b.y, 0.f);
    v.z = fmaxf((A0.z + A1.z) * inv + b.z, 0.f);
    v.w = fmaxf((A0.w + A1.w) * inv + b.w, 0.f);

    int g = batch[node];
    int* p = (int*)(pool + (size_t)g * HID + lane * 4);
    // values >= 0 so signed-int compare is order-preserving
    atomicMax(p + 0, __float_as_int(v.x));
    atomicMax(p + 1, __float_as_int(v.y));
    atomicMax(p + 2, __float_as_int(v.z));
    atomicMax(p + 3, __float_as_int(v.w));
}

// ---------------- launch ----------------
extern "C" void kernel_launch(void* const* d_in, const int* in_sizes, int n_in,
                              void* d_out, int out_size) {
    const float* x       = (const float*)d_in[0];   // [N, 1024]
    const float* W       = (const float*)d_in[1];   // [1024, 128]
    const float* att_src = (const float*)d_in[2];   // [128]
    const float* att_dst = (const float*)d_in[3];   // [128]
    const float* bias    = (const float*)d_in[4];   // [128]
    const int*   ei      = (const int*)d_in[5];     // [2, E]
    const int*   batch   = (const int*)d_in[6];     // [N]
    float* pool = (float*)d_out;                    // [G, 128]

    const int N = in_sizes[0] / IN_DIM;
    const int E = in_sizes[5] / 2;
    const int tot = E + N;
    const int nb = (N + 255) / 256;

    cudaFuncSetAttribute(gemm_tf32_kernel,
                         cudaFuncAttributeMaxDynamicSharedMemorySize, GEMM_SMEM);

    // pool init + W permute + edge count
    combo_kernel<<<(E + 255) / 256, 256>>>(W, ei, E, pool);
    // GEMM h = x @ W (+ fused attdot)
    gemm_tf32_kernel<<<(N + 127) / 128, 128, GEMM_SMEM>>>(x, att_src, att_dst, N);
    // CSR offsets (parallel scan) + scatter
    scan1_kernel<<<nb, 256>>>(N);
    scan2_kernel<<<1, 256>>>(nb, N);
    scan3_kernel<<<nb, 256>>>(N);
    scatter_kernel<<<(tot + 255) / 256, 256>>>(ei, E, N);
    // fused softmax + aggregate + relu + pool
    gat_kernel<<<(N * 32 + 255) / 256, 256>>>(bias, batch, pool, N);
}

// round 6
// speedup vs baseline: 2.6219x; 1.1048x over previous
#include <cuda_runtime.h>
#include <cuda_fp16.h>
#include <math.h>
#include <stdint.h>

#define MAXN     50000
#define MAXE     1600000
#define IN_DIM   1024
#define HID      128
#define MAXG     64
#define MAXETOT  (MAXE + MAXN)
#define NKB      (IN_DIM / 16)   // 64 k-blocks of 16

// GEMM pipeline config: 128 threads, 4 warps (2m x 2n), warp tile 64x64
#define S_STAGES  4
#define AS_STRIDE 20                         // floats per A row (16 used, pad to 20)
#define AS_FLOATS (128 * AS_STRIDE)          // per stage
#define AS_BYTES  (AS_FLOATS * 4)
#define BS_F2     (8 * 132)                  // per stage (slot-major, padded)
#define BS_BYTES  (BS_F2 * 8)
#define GEMM_SMEM (S_STAGES * (AS_BYTES + BS_BYTES))

// ---------------- device scratch (static; no allocations) ----------------
__device__ __half g_hh[(size_t)MAXN * HID];   // h in fp16 (gather copy)
__device__ int2   g_ps[MAXETOT];              // per-edge {p bits, src id}, CSR order
__device__ float  g_asrc[MAXN];
__device__ float  g_adst[MAXN];
__device__ int    g_cnt[MAXN];                // per-dst in-degree (re-zeroed by scan1)
__device__ int    g_off[MAXN + 1];            // CSR offsets
__device__ int    g_cur[MAXN];                // scatter cursors
__device__ int    g_bsum[256];                // scan block sums
__device__ float2 g_Wp[NKB * 8 * 128];        // W permuted tf32 pairs

// ---------------- helpers ----------------
__device__ __forceinline__ float tf32r(float x) {
    unsigned int t;
    asm("cvt.rna.tf32.f32 %0, %1;" : "=r"(t) : "f"(x));
    return __uint_as_float(t);
}

// ---------------- kernels ----------------

// combo: pool=0, W permute, per-dst edge count.
__global__ void combo_kernel(const float* __restrict__ W,
                             const int* __restrict__ ei, int E, float* pool) {
    int i = blockIdx.x * blockDim.x + threadIdx.x;
    if (i < MAXG * HID) pool[i] = 0.f;
    if (i < NKB * 8 * 128) {
        int n = i & 127;
        int s = (i >> 7) & 7;
        int kb = i >> 10;
        int ks = ((s >> 2) << 3) + (s & 3);
        int k0 = kb * 16 + ks;
        g_Wp[i] = make_float2(tf32r(W[(size_t)k0 * HID + n]),
                              tf32r(W[(size_t)(k0 + 4) * HID + n]));
    }
    if (i < E) atomicAdd(&g_cnt[ei[E + i]], 1);
}

// TF32 tensor-core GEMM with fused attdot epilogue. h written fp16 only.
__global__ __launch_bounds__(128, 2) void gemm_tf32_kernel(
        const float* __restrict__ A,
        const float* __restrict__ att_src,
        const float* __restrict__ att_dst, int M) {
    extern __shared__ float smem[];
    float2* BsAll = (float2*)(smem + S_STAGES * AS_FLOATS);

    const int tid  = threadIdx.x;
    const int lane = tid & 31;
    const int warp = tid >> 5;
    const int gid  = lane >> 2;   // 0..7
    const int tig  = lane & 3;    // 0..3
    const int wm   = (warp & 1) * 64;
    const int wn   = (warp >> 1) * 64;
    const int block_row = blockIdx.x * 128;

    uint32_t sbase = (uint32_t)__cvta_generic_to_shared(smem);

    const int lrow = tid >> 2;        // 0..31
    const int lq   = tid & 3;         // 0..3

#define GEMM_ISSUE(kb_, s_) do {                                                \
    _Pragma("unroll")                                                           \
    for (int ii = 0; ii < 4; ii++) {                                            \
        int row_ = ii * 32 + lrow;                                              \
        int gr_ = block_row + row_;                                             \
        const float* asrc_ = A + (size_t)gr_ * IN_DIM + (kb_) * 16 + lq * 4;    \
        int sz_ = (gr_ < M) ? 16 : 0;                                           \
        uint32_t ad_ = sbase + (s_) * AS_BYTES + (row_ * AS_STRIDE + lq * 4) * 4; \
        asm volatile("cp.async.cg.shared.global [%0], [%1], 16, %2;"            \
                     :: "r"(ad_), "l"(asrc_), "r"(sz_));                        \
    }                                                                           \
    _Pragma("unroll")                                                           \
    for (int jj = 0; jj < 4; jj++) {                                            \
        int f2i_ = 2 * (jj * 128 + tid);                                        \
        int slot_ = f2i_ >> 7, nn_ = f2i_ & 127;                                \
        const float2* bsrc_ = g_Wp + (size_t)(kb_) * 1024 + f2i_;               \
        uint32_t bd_ = sbase + S_STAGES * AS_BYTES + (s_) * BS_BYTES +          \
                       (slot_ * 132 + nn_) * 8;                                 \
        asm volatile("cp.async.cg.shared.global [%0], [%1], 16;"                \
                     :: "r"(bd_), "l"(bsrc_));                                  \
    }                                                                           \
} while (0)

    float acc[4][8][4];
#pragma unroll
    for (int mt = 0; mt < 4; mt++)
#pragma unroll
        for (int nt = 0; nt < 8; nt++)
#pragma unroll
            for (int i = 0; i < 4; i++) acc[mt][nt][i] = 0.f;

#pragma unroll
    for (int s = 0; s < S_STAGES - 1; s++) {
        GEMM_ISSUE(s, s);
        asm volatile("cp.async.commit_group;");
    }

#pragma unroll 1
    for (int kb = 0; kb < NKB; kb++) {
        asm volatile("cp.async.wait_group %0;" :: "n"(S_STAGES - 2));
        __syncthreads();

        int nk = kb + S_STAGES - 1;
        if (nk < NKB) GEMM_ISSUE(nk, nk % S_STAGES);
        asm volatile("cp.async.commit_group;");

        const int buf = kb % S_STAGES;
        const float* As_ = smem + buf * AS_FLOATS;
        const float2* Bs_ = BsAll + buf * BS_F2;

#pragma unroll
        for (int ks = 0; ks < 2; ks++) {
            float a0[4], a1[4], a2[4], a3[4];
#pragma unroll
            for (int mt = 0; mt < 4; mt++) {
                int r0 = wm + mt * 16 + gid;
                a0[mt] = As_[r0 * AS_STRIDE + ks * 8 + tig];
                a1[mt] = As_[(r0 + 8) * AS_STRIDE + ks * 8 + tig];
                a2[mt] = As_[r0 * AS_STRIDE + ks * 8 + tig + 4];
                a3[mt] = As_[(r0 + 8) * AS_STRIDE + ks * 8 + tig + 4];
            }
            float2 bfr[8];
#pragma unroll
            for (int nt = 0; nt < 8; nt++)
                bfr[nt] = Bs_[(ks * 4 + tig) * 132 + wn + nt * 8 + gid];
#pragma unroll
            for (int mt = 0; mt < 4; mt++)
#pragma unroll
                for (int nt = 0; nt < 8; nt++) {
                    asm("mma.sync.aligned.m16n8k8.row.col.f32.tf32.tf32.f32 "
                        "{%0,%1,%2,%3}, {%4,%5,%6,%7}, {%8,%9}, {%0,%1,%2,%3};"
                        : "+f"(acc[mt][nt][0]), "+f"(acc[mt][nt][1]),
                          "+f"(acc[mt][nt][2]), "+f"(acc[mt][nt][3])
                        : "r"(__float_as_uint(a0[mt])),
                          "r"(__float_as_uint(a1[mt])),
                          "r"(__float_as_uint(a2[mt])),
                          "r"(__float_as_uint(a3[mt])),
                          "r"(__float_as_uint(bfr[nt].x)),
                          "r"(__float_as_uint(bfr[nt].y)));
                }
        }
    }
#undef GEMM_ISSUE

    // ---- epilogue: write h (fp16), fused attdot ----
    float psrc[4][2], pdst[4][2];
#pragma unroll
    for (int mt = 0; mt < 4; mt++) {
        psrc[mt][0] = psrc[mt][1] = 0.f;
        pdst[mt][0] = pdst[mt][1] = 0.f;
    }

#pragma unroll
    for (int mt = 0; mt < 4; mt++) {
        int row0 = block_row + wm + mt * 16 + gid;
#pragma unroll
        for (int nt = 0; nt < 8; nt++) {
            int col = wn + nt * 8 + tig * 2;
            float s0 = __ldg(att_src + col), s1 = __ldg(att_src + col + 1);
            float d0 = __ldg(att_dst + col), d1 = __ldg(att_dst + col + 1);
            psrc[mt][0] += acc[mt][nt][0] * s0 + acc[mt][nt][1] * s1;
            pdst[mt][0] += acc[mt][nt][0] * d0 + acc[mt][nt][1] * d1;
            psrc[mt][1] += acc[mt][nt][2] * s0 + acc[mt][nt][3] * s1;
            pdst[mt][1] += acc[mt][nt][2] * d0 + acc[mt][nt][3] * d1;
            if (row0 < M)
                *(__half2*)&g_hh[(size_t)row0 * HID + col] =
                    __float22half2_rn(make_float2(acc[mt][nt][0], acc[mt][nt][1]));
            if (row0 + 8 < M)
                *(__half2*)&g_hh[(size_t)(row0 + 8) * HID + col] =
                    __float22half2_rn(make_float2(acc[mt][nt][2], acc[mt][nt][3]));
        }
    }

#pragma unroll
    for (int mt = 0; mt < 4; mt++)
#pragma unroll
        for (int hf = 0; hf < 2; hf++) {
            psrc[mt][hf] += __shfl_xor_sync(0xffffffffu, psrc[mt][hf], 1);
            psrc[mt][hf] += __shfl_xor_sync(0xffffffffu, psrc[mt][hf], 2);
            pdst[mt][hf] += __shfl_xor_sync(0xffffffffu, pdst[mt][hf], 1);
            pdst[mt][hf] += __shfl_xor_sync(0xffffffffu, pdst[mt][hf], 2);
        }

    __syncthreads();
    float* rs = smem;          // [128][2]
    float* rd = smem + 256;    // [128][2]
    int nh = warp >> 1;
    if (tig == 0) {
#pragma unroll
        for (int mt = 0; mt < 4; mt++) {
#pragma unroll
            for (int hf = 0; hf < 2; hf++) {
                int rl = wm + mt * 16 + gid + hf * 8;
                rs[rl * 2 + nh] = psrc[mt][hf];
                rd[rl * 2 + nh] = pdst[mt][hf];
            }
        }
    }
    __syncthreads();
    int r = block_row + tid;
    if (r < M) {
        g_asrc[r] = rs[tid * 2] + rs[tid * 2 + 1];
        g_adst[r] = rd[tid * 2] + rd[tid * 2 + 1];
    }
}

// scan1: per-block (256 nodes) local exclusive scan of (cnt+1); block sums.
__global__ __launch_bounds__(256) void scan1_kernel(int N) {
    __shared__ int ws[8];
    int t = threadIdx.x, b = blockIdx.x;
    int i = b * 256 + t;
    int c = 0;
    if (i < N) { c = g_cnt[i] + 1; g_cnt[i] = 0; }   // +1 = self loop
    int lane = t & 31, w = t >> 5;
    int v = c;
#pragma unroll
    for (int o = 1; o < 32; o <<= 1) {
        int u = __shfl_up_sync(0xffffffffu, v, o);
        if (lane >= o) v += u;
    }
    if (lane == 31) ws[w] = v;
    __syncthreads();
    if (w == 0) {
        int x = (lane < 8) ? ws[lane] : 0;
#pragma unroll
        for (int o = 1; o < 8; o <<= 1) {
            int u = __shfl_up_sync(0xffffffffu, x, o);
            if (lane >= o) x += u;
        }
        if (lane < 8) ws[lane] = x;
    }
    __syncthreads();
    int excl = v - c + (w > 0 ? ws[w - 1] : 0);
    if (i < N) g_off[i] = excl;
    if (t == 255) g_bsum[b] = excl + c;
}

// scan23: each block reduces g_bsum itself (prefix + total), applies.
__global__ __launch_bounds__(256) void scan23_kernel(int nb, int N) {
    __shared__ int shp[8], sht[8];
    int t = threadIdx.x, b = blockIdx.x;
    int accp = 0, acct = 0;
    for (int i = t; i < nb; i += 256) {
        int v = g_bsum[i];
        acct += v;
        if (i < b) accp += v;
    }
    int lane = t & 31, w = t >> 5;
#pragma unroll
    for (int o = 16; o; o >>= 1) {
        accp += __shfl_xor_sync(0xffffffffu, accp, o);
        acct += __shfl_xor_sync(0xffffffffu, acct, o);
    }
    if (lane == 0) { shp[w] = accp; sht[w] = acct; }
    __syncthreads();
    if (t == 0) {
        int p = 0, tt = 0;
#pragma unroll
        for (int k = 0; k < 8; k++) { p += shp[k]; tt += sht[k]; }
        shp[0] = p; sht[0] = tt;
    }
    __syncthreads();
    int pre = shp[0];
    int i = b * 256 + t;
    if (i < N) {
        int o = g_off[i] + pre;
        g_off[i] = o;
        g_cur[i] = o;
    }
    if (b == nb - 1 && t == 0) g_off[N] = sht[0];
}

// scatter edges (and self loops) into CSR order: src into g_ps[.].y
__global__ void scatter_kernel(const int* __restrict__ ei, int E, int N) {
    int i = blockIdx.x * blockDim.x + threadIdx.x;
    int tot = E + N;
    if (i >= tot) return;
    int s, d;
    if (i < E) { s = ei[i]; d = ei[E + i]; }
    else       { s = d = i - E; }
    int pos = atomicAdd(&g_cur[d], 1);
    g_ps[pos].y = s;
}

// fused GAT: warp per dst node. p=exp(leakyrelu(e)) (no max shift — e bounded),
// weighted aggregation from fp16 h, bias+relu, global max pool.
__global__ __launch_bounds__(256) void gat_kernel(const float* __restrict__ bias,
                                                  const int* __restrict__ batch,
                                                  float* pool, int N) {
    int node = (blockIdx.x * blockDim.x + threadIdx.x) >> 5;
    int lane = threadIdx.x & 31;
    if (node >= N) return;

    int base = g_off[node];
    int deg  = g_off[node + 1] - base;
    float adst = g_adst[node];

    // merged pass: p = exp(leaky_relu(a_src[s] + adst)); warp sum
    float den = 0.f;
    for (int j = lane; j < deg; j += 32) {
        int s = g_ps[base + j].y;
        float e = g_asrc[s] + adst;
        e = e > 0.f ? e : 0.2f * e;
        float p = __expf(e);
        g_ps[base + j].x = __float_as_int(p);
        den += p;
    }
#pragma unroll
    for (int o = 16; o; o >>= 1)
        den += __shfl_xor_sync(0xffffffffu, den, o);

    // aggregation: acc = sum p * h[s] (fp16 gather, unroll 4)
    const uint2* hh = (const uint2*)g_hh;   // 32 uint2 per row
    const int2* ps = g_ps;
    float4 A0 = make_float4(0.f, 0.f, 0.f, 0.f);
    float4 A1 = make_float4(0.f, 0.f, 0.f, 0.f);
    int j = 0;
    for (; j + 4 <= deg; j += 4) {
        int2 e0 = ps[base + j],     e1 = ps[base + j + 1];
        int2 e2 = ps[base + j + 2], e3 = ps[base + j + 3];
        float p0 = __int_as_float(e0.x), p1 = __int_as_float(e1.x);
        float p2 = __int_as_float(e2.x), p3 = __int_as_float(e3.x);
        uint2 v0 = hh[(size_t)e0.y * 32 + lane];
        uint2 v1 = hh[(size_t)e1.y * 32 + lane];
        uint2 v2 = hh[(size_t)e2.y * 32 + lane];
        uint2 v3 = hh[(size_t)e3.y * 32 + lane];
        float2 f;
        f = __half22float2(*(__half2*)&v0.x); A0.x = fmaf(p0, f.x, A0.x); A0.y = fmaf(p0, f.y, A0.y);
        f = __half22float2(*(__half2*)&v0.y); A0.z = fmaf(p0, f.x, A0.z); A0.w = fmaf(p0, f.y, A0.w);
        f = __half22float2(*(__half2*)&v1.x); A1.x = fmaf(p1, f.x, A1.x); A1.y = fmaf(p1, f.y, A1.y);
        f = __half22float2(*(__half2*)&v1.y); A1.z = fmaf(p1, f.x, A1.z); A1.w = fmaf(p1, f.y, A1.w);
        f = __half22float2(*(__half2*)&v2.x); A0.x = fmaf(p2, f.x, A0.x); A0.y = fmaf(p2, f.y, A0.y);
        f = __half22float2(*(__half2*)&v2.y); A0.z = fmaf(p2, f.x, A0.z); A0.w = fmaf(p2, f.y, A0.w);
        f = __half22float2(*(__half2*)&v3.x); A1.x = fmaf(p3, f.x, A1.x); A1.y = fmaf(p3, f.y, A1.y);
        f = __half22float2(*(__half2*)&v3.y); A1.z = fmaf(p3, f.x, A1.z); A1.w = fmaf(p3, f.y, A1.w);
    }
    for (; j < deg; j++) {
        int2 e0 = ps[base + j];
        float p0 = __int_as_float(e0.x);
        uint2 v0 = hh[(size_t)e0.y * 32 + lane];
        float2 f;
        f = __half22float2(*(__half2*)&v0.x); A0.x = fmaf(p0, f.x, A0.x); A0.y = fmaf(p0, f.y, A0.y);
        f = __half22float2(*(__half2*)&v0.y); A0.z = fmaf(p0, f.x, A0.z); A0.w = fmaf(p0, f.y, A0.w);
    }

    float inv = 1.f / den;
    float4 b = ((const float4*)bias)[lane];
    float4 v;
    v.x = fmaxf((A0.x + A1.x) * inv + b.x, 0.f);
    v.y = fmaxf((A0.y + A1.y) * inv + b.y, 0.f);
    v.z = fmaxf((A0.z + A1.z) * inv + b.z, 0.f);
    v.w = fmaxf((A0.w + A1.w) * inv + b.w, 0.f);

    int g = batch[node];
    int* p = (int*)(pool + (size_t)g * HID + lane * 4);
    // values >= 0 so signed-int compare is order-preserving
    atomicMax(p + 0, __float_as_int(v.x));
    atomicMax(p + 1, __float_as_int(v.y));
    atomicMax(p + 2, __float_as_int(v.z));
    atomicMax(p + 3, __float_as_int(v.w));
}

// ---------------- launch ----------------
extern "C" void kernel_launch(void* const* d_in, const int* in_sizes, int n_in,
                              void* d_out, int out_size) {
    const float* x       = (const float*)d_in[0];   // [N, 1024]
    const float* W       = (const float*)d_in[1];   // [1024, 128]
    const float* att_src = (const float*)d_in[2];   // [128]
    const float* att_dst = (const float*)d_in[3];   // [128]
    const float* bias    = (const float*)d_in[4];   // [128]
    const int*   ei      = (const int*)d_in[5];     // [2, E]
    const int*   batch   = (const int*)d_in[6];     // [N]
    float* pool = (float*)d_out;                    // [G, 128]

    const int N = in_sizes[0] / IN_DIM;
    const int E = in_sizes[5] / 2;
    const int tot = E + N;
    const int nb = (N + 255) / 256;

    cudaFuncSetAttribute(gemm_tf32_kernel,
                         cudaFuncAttributeMaxDynamicSharedMemorySize, GEMM_SMEM);

    // fork-join: CSR build (stream s2) overlaps the GEMM (main stream).
    // Streams/events are created fresh each call (host-side only, no device
    // memory) and intentionally not destroyed: kernel_launch runs only a few
    // times (correctness + capture); destroying a capture-participating
    // stream mid-capture would invalidate the graph.
    cudaStream_t s2;
    cudaStreamCreateWithFlags(&s2, cudaStreamNonBlocking);
    cudaEvent_t e1, e2;
    cudaEventCreateWithFlags(&e1, cudaEventDisableTiming);
    cudaEventCreateWithFlags(&e2, cudaEventDisableTiming);

    // common root: pool init + W permute + edge count
    combo_kernel<<<(E + 255) / 256, 256>>>(W, ei, E, pool);
    cudaEventRecord(e1, 0);

    // branch A (s2): CSR offsets + scatter
    cudaStreamWaitEvent(s2, e1, 0);
    scan1_kernel<<<nb, 256, 0, s2>>>(N);
    scan23_kernel<<<nb, 256, 0, s2>>>(nb, N);
    scatter_kernel<<<(tot + 255) / 256, 256, 0, s2>>>(ei, E, N);
    cudaEventRecord(e2, s2);

    // branch B (main): GEMM h = x @ W (+ fused attdot)
    gemm_tf32_kernel<<<(N + 127) / 128, 128, GEMM_SMEM>>>(x, att_src, att_dst, N);

    // join, then fused softmax + aggregate + relu + pool
    cudaStreamWaitEvent(0, e2, 0);
    gat_kernel<<<(N * 32 + 255) / 256, 256>>>(bias, batch, pool, N);
}

// round 9
// speedup vs baseline: 2.8126x; 1.0727x over previous
#include <cuda_runtime.h>
#include <cuda_fp16.h>
#include <math.h>
#include <stdint.h>

#define MAXN     50000
#define MAXE     1600000
#define IN_DIM   1024
#define HID      128
#define MAXG     64
#define MAXETOT  (MAXE + MAXN)

// fp16 mma GEMM config: 256 threads, 8 warps (4m x 2n), warp tile 32x64, BK=32
#define NCH      (IN_DIM / 32)      // 32 chunks of k=32
#define A_ROWB   80                 // bytes per A smem row (64 used + 16 pad)
#define A_STG    (128 * A_ROWB)     // 10240 per stage
#define B_ROWB   544                // bytes per B kpair row (512 used + 32 pad)
#define B_STG    (16 * B_ROWB)      // 8704 per stage
#define SM_B0    (2 * A_STG)        // B stages after 2 A stages
#define SM_TOT   (2 * A_STG + 2 * B_STG)   // 37888 bytes

// ---------------- device scratch (static; no allocations) ----------------
__device__ __half g_hh[(size_t)MAXN * HID];   // h in fp16 (gather copy)
__device__ __half2 g_Wp2[512 * 128];          // W as half2 kpairs: [kpair][n]
__device__ int2   g_ps[MAXETOT];              // per-edge {p bits, src id}, CSR order
__device__ float  g_asrc[MAXN];
__device__ float  g_adst[MAXN];
__device__ int    g_cnt[MAXN];                // per-dst in-degree (re-zeroed by scan1)
__device__ int    g_off[MAXN + 1];            // CSR offsets
__device__ int    g_cur[MAXN];                // scatter cursors
__device__ int    g_bsum[256];                // scan block sums

// ---------------- kernels ----------------

// combo: pool=0, W -> half2 kpair layout, per-dst edge count.
__global__ void combo_kernel(const float* __restrict__ W,
                             const int* __restrict__ ei, int E, float* pool) {
    int i = blockIdx.x * blockDim.x + threadIdx.x;
    if (i < MAXG * HID) pool[i] = 0.f;
    if (i < 512 * 128) {
        int n = i & 127;
        int p = i >> 7;
        g_Wp2[i] = __floats2half2_rn(W[(size_t)(2 * p) * HID + n],
                                     W[(size_t)(2 * p + 1) * HID + n]);
    }
    if (i < E) atomicAdd(&g_cnt[ei[E + i]], 1);
}

// fp16 mma.sync m16n8k16 GEMM with fused attdot epilogue. h written fp16.
// 256 threads, 8 warps (warp&3 = m quarter, warp>>2 = n half), BK=32, 2-stage.
__global__ __launch_bounds__(256) void gemm_f16_kernel(
        const float* __restrict__ A,
        const float* __restrict__ att_src,
        const float* __restrict__ att_dst, int M) {
    __shared__ char smem[SM_TOT];
    const uint32_t sbase = (uint32_t)__cvta_generic_to_shared(smem);

    const int tid  = threadIdx.x;
    const int lane = tid & 31;
    const int warp = tid >> 5;
    const int gid  = lane >> 2;   // 0..7
    const int tig  = lane & 3;    // 0..3
    const int wm   = (warp & 3) * 32;
    const int wn   = (warp >> 2) * 64;
    const int block_row = blockIdx.x * 128;

    // A LDG mapping: iter i: row = i*32 + (tid>>3), cols (tid&7)*4 (float4)
    const int ar = tid >> 3;   // 0..31
    const int aq = tid & 7;    // 0..7
    bool avalid[4];
    const float* aptr[4];
#pragma unroll
    for (int i = 0; i < 4; i++) {
        int gr = block_row + i * 32 + ar;
        avalid[i] = gr < M;
        aptr[i] = A + (size_t)(avalid[i] ? gr : 0) * IN_DIM + aq * 4;
    }

    float4 areg[4];
#define LDA(c_) do {                                                         \
    _Pragma("unroll")                                                        \
    for (int i = 0; i < 4; i++)                                              \
        areg[i] = avalid[i] ? *(const float4*)(aptr[i] + (c_) * 32)          \
                            : make_float4(0.f, 0.f, 0.f, 0.f);               \
} while (0)
#define STA(buf_) do {                                                       \
    _Pragma("unroll")                                                        \
    for (int i = 0; i < 4; i++) {                                            \
        __half2 h0 = __floats2half2_rn(areg[i].x, areg[i].y);                \
        __half2 h1 = __floats2half2_rn(areg[i].z, areg[i].w);                \
        uint2 u; u.x = *(uint32_t*)&h0; u.y = *(uint32_t*)&h1;               \
        *(uint2*)(smem + (buf_) * A_STG + (i * 32 + ar) * A_ROWB + aq * 8) = u; \
    }                                                                        \
} while (0)
#define LDB(c_, buf_) do {                                                   \
    _Pragma("unroll")                                                        \
    for (int j = 0; j < 2; j++) {                                            \
        int idx = j * 256 + tid;                                             \
        int brow = idx >> 5;                                                 \
        int bcol = idx & 31;                                                 \
        const __half2* src = g_Wp2 + (size_t)(c_) * 2048 + idx * 4;          \
        uint32_t dst = sbase + SM_B0 + (buf_) * B_STG + brow * B_ROWB + bcol * 16; \
        asm volatile("cp.async.cg.shared.global [%0], [%1], 16;"             \
                     :: "r"(dst), "l"(src));                                 \
    }                                                                        \
    asm volatile("cp.async.commit_group;");                                  \
} while (0)

    float acc[2][8][4];
#pragma unroll
    for (int mt = 0; mt < 2; mt++)
#pragma unroll
        for (int nt = 0; nt < 8; nt++)
#pragma unroll
            for (int i = 0; i < 4; i++) acc[mt][nt][i] = 0.f;

    // prologue
    LDA(0); STA(0); LDB(0, 0);

#pragma unroll 1
    for (int c = 0; c < NCH; c++) {
        const int buf = c & 1;
        if (c < NCH - 1) LDA(c + 1);
        asm volatile("cp.async.wait_group 0;");
        __syncthreads();

        const char* As = smem + buf * A_STG;
        const char* Bs = smem + SM_B0 + buf * B_STG;
#pragma unroll
        for (int ks = 0; ks < 2; ks++) {
            uint32_t afr[2][4];
#pragma unroll
            for (int mt = 0; mt < 2; mt++) {
                int r0 = wm + mt * 16 + gid;
                afr[mt][0] = *(const uint32_t*)(As + r0 * A_ROWB + (ks * 8 + tig) * 4);
                afr[mt][1] = *(const uint32_t*)(As + (r0 + 8) * A_ROWB + (ks * 8 + tig) * 4);
                afr[mt][2] = *(const uint32_t*)(As + r0 * A_ROWB + (ks * 8 + 4 + tig) * 4);
                afr[mt][3] = *(const uint32_t*)(As + (r0 + 8) * A_ROWB + (ks * 8 + 4 + tig) * 4);
            }
            uint32_t bfr[8][2];
#pragma unroll
            for (int nt = 0; nt < 8; nt++) {
                int col = wn + nt * 8 + gid;
                bfr[nt][0] = *(const uint32_t*)(Bs + (ks * 8 + tig) * B_ROWB + col * 4);
                bfr[nt][1] = *(const uint32_t*)(Bs + (ks * 8 + 4 + tig) * B_ROWB + col * 4);
            }
#pragma unroll
            for (int mt = 0; mt < 2; mt++)
#pragma unroll
                for (int nt = 0; nt < 8; nt++) {
                    asm("mma.sync.aligned.m16n8k16.row.col.f32.f16.f16.f32 "
                        "{%0,%1,%2,%3}, {%4,%5,%6,%7}, {%8,%9}, {%0,%1,%2,%3};"
                        : "+f"(acc[mt][nt][0]), "+f"(acc[mt][nt][1]),
                          "+f"(acc[mt][nt][2]), "+f"(acc[mt][nt][3])
                        : "r"(afr[mt][0]), "r"(afr[mt][1]),
                          "r"(afr[mt][2]), "r"(afr[mt][3]),
                          "r"(bfr[nt][0]), "r"(bfr[nt][1]));
                }
        }

        if (c < NCH - 1) {
            STA(buf ^ 1);
            LDB(c + 1, buf ^ 1);
        }
    }
#undef LDA
#undef STA
#undef LDB

    // ---- epilogue: write h (fp16), fused attdot ----
    float psrc[2][2], pdst[2][2];
#pragma unroll
    for (int mt = 0; mt < 2; mt++) {
        psrc[mt][0] = psrc[mt][1] = 0.f;
        pdst[mt][0] = pdst[mt][1] = 0.f;
    }

#pragma unroll
    for (int mt = 0; mt < 2; mt++) {
        int row0 = block_row + wm + mt * 16 + gid;
#pragma unroll
        for (int nt = 0; nt < 8; nt++) {
            int col = wn + nt * 8 + tig * 2;
            float s0 = __ldg(att_src + col), s1 = __ldg(att_src + col + 1);
            float d0 = __ldg(att_dst + col), d1 = __ldg(att_dst + col + 1);
            psrc[mt][0] += acc[mt][nt][0] * s0 + acc[mt][nt][1] * s1;
            pdst[mt][0] += acc[mt][nt][0] * d0 + acc[mt][nt][1] * d1;
            psrc[mt][1] += acc[mt][nt][2] * s0 + acc[mt][nt][3] * s1;
            pdst[mt][1] += acc[mt][nt][2] * d0 + acc[mt][nt][3] * d1;
            if (row0 < M) {
                __half2 hv = __floats2half2_rn(acc[mt][nt][0], acc[mt][nt][1]);
                *(__half2*)&g_hh[(size_t)row0 * HID + col] = hv;
            }
            if (row0 + 8 < M) {
                __half2 hv = __floats2half2_rn(acc[mt][nt][2], acc[mt][nt][3]);
                *(__half2*)&g_hh[(size_t)(row0 + 8) * HID + col] = hv;
            }
        }
    }

    // quad reduce (over tig lanes)
#pragma unroll
    for (int mt = 0; mt < 2; mt++)
#pragma unroll
        for (int hf = 0; hf < 2; hf++) {
            psrc[mt][hf] += __shfl_xor_sync(0xffffffffu, psrc[mt][hf], 1);
            psrc[mt][hf] += __shfl_xor_sync(0xffffffffu, psrc[mt][hf], 2);
            pdst[mt][hf] += __shfl_xor_sync(0xffffffffu, pdst[mt][hf], 1);
            pdst[mt][hf] += __shfl_xor_sync(0xffffffffu, pdst[mt][hf], 2);
        }

    __syncthreads();   // compute done everywhere; reuse smem for reduction
    float* rs = (float*)smem;          // [128][2]
    float* rd = (float*)smem + 256;    // [128][2]
    int nh = warp >> 2;
    if (tig == 0) {
#pragma unroll
        for (int mt = 0; mt < 2; mt++)
#pragma unroll
            for (int hf = 0; hf < 2; hf++) {
                int rl = wm + mt * 16 + gid + hf * 8;
                rs[rl * 2 + nh] = psrc[mt][hf];
                rd[rl * 2 + nh] = pdst[mt][hf];
            }
    }
    __syncthreads();
    if (tid < 128) {
        int r = block_row + tid;
        if (r < M) {
            g_asrc[r] = rs[tid * 2] + rs[tid * 2 + 1];
            g_adst[r] = rd[tid * 2] + rd[tid * 2 + 1];
        }
    }
}

// scan1: per-block (256 nodes) local exclusive scan of (cnt+1); block sums.
__global__ __launch_bounds__(256) void scan1_kernel(int N) {
    __shared__ int ws[8];
    int t = threadIdx.x, b = blockIdx.x;
    int i = b * 256 + t;
    int c = 0;
    if (i < N) { c = g_cnt[i] + 1; g_cnt[i] = 0; }   // +1 = self loop
    int lane = t & 31, w = t >> 5;
    int v = c;
#pragma unroll
    for (int o = 1; o < 32; o <<= 1) {
        int u = __shfl_up_sync(0xffffffffu, v, o);
        if (lane >= o) v += u;
    }
    if (lane == 31) ws[w] = v;
    __syncthreads();
    if (w == 0) {
        int x = (lane < 8) ? ws[lane] : 0;
#pragma unroll
        for (int o = 1; o < 8; o <<= 1) {
            int u = __shfl_up_sync(0xffffffffu, x, o);
            if (lane >= o) x += u;
        }
        if (lane < 8) ws[lane] = x;
    }
    __syncthreads();
    int excl = v - c + (w > 0 ? ws[w - 1] : 0);
    if (i < N) g_off[i] = excl;
    if (t == 255) g_bsum[b] = excl + c;
}

// scan23: each block reduces g_bsum itself (prefix + total), applies.
__global__ __launch_bounds__(256) void scan23_kernel(int nb, int N) {
    __shared__ int shp[8], sht[8];
    int t = threadIdx.x, b = blockIdx.x;
    int accp = 0, acct = 0;
    for (int i = t; i < nb; i += 256) {
        int v = g_bsum[i];
        acct += v;
        if (i < b) accp += v;
    }
    int lane = t & 31, w = t >> 5;
#pragma unroll
    for (int o = 16; o; o >>= 1) {
        accp += __shfl_xor_sync(0xffffffffu, accp, o);
        acct += __shfl_xor_sync(0xffffffffu, acct, o);
    }
    if (lane == 0) { shp[w] = accp; sht[w] = acct; }
    __syncthreads();
    if (t == 0) {
        int p = 0, tt = 0;
#pragma unroll
        for (int k = 0; k < 8; k++) { p += shp[k]; tt += sht[k]; }
        shp[0] = p; sht[0] = tt;
    }
    __syncthreads();
    int pre = shp[0];
    int i = b * 256 + t;
    if (i < N) {
        int o = g_off[i] + pre;
        g_off[i] = o;
        g_cur[i] = o;
    }
    if (b == nb - 1 && t == 0) g_off[N] = sht[0];
}

// scatter edges (and self loops) into CSR order: src into g_ps[.].y
__global__ void scatter_kernel(const int* __restrict__ ei, int E, int N) {
    int i = blockIdx.x * blockDim.x + threadIdx.x;
    int tot = E + N;
    if (i >= tot) return;
    int s, d;
    if (i < E) { s = ei[i]; d = ei[E + i]; }
    else       { s = d = i - E; }
    int pos = atomicAdd(&g_cur[d], 1);
    g_ps[pos].y = s;
}

// fused GAT: warp per dst node. p=exp(leakyrelu(e)) (no max shift — e bounded),
// weighted aggregation from fp16 h, bias+relu, global max pool.
__global__ __launch_bounds__(256) void gat_kernel(const float* __restrict__ bias,
                                                  const int* __restrict__ batch,
                                                  float* pool, int N) {
    int node = (blockIdx.x * blockDim.x + threadIdx.x) >> 5;
    int lane = threadIdx.x & 31;
    if (node >= N) return;

    int base = g_off[node];
    int deg  = g_off[node + 1] - base;
    float adst = g_adst[node];

    float den = 0.f;
    for (int j = lane; j < deg; j += 32) {
        int s = g_ps[base + j].y;
        float e = g_asrc[s] + adst;
        e = e > 0.f ? e : 0.2f * e;
        float p = __expf(e);
        g_ps[base + j].x = __float_as_int(p);
        den += p;
    }
#pragma unroll
    for (int o = 16; o; o >>= 1)
        den += __shfl_xor_sync(0xffffffffu, den, o);

    const uint2* hh = (const uint2*)g_hh;   // 32 uint2 per row
    const int2* ps = g_ps;
    float4 A0 = make_float4(0.f, 0.f, 0.f, 0.f);
    float4 A1 = make_float4(0.f, 0.f, 0.f, 0.f);
    int j = 0;
    for (; j + 4 <= deg; j += 4) {
        int2 e0 = ps[base + j],     e1 = ps[base + j + 1];
        int2 e2 = ps[base + j + 2], e3 = ps[base + j + 3];
        float p0 = __int_as_float(e0.x), p1 = __int_as_float(e1.x);
        float p2 = __int_as_float(e2.x), p3 = __int_as_float(e3.x);
        uint2 v0 = hh[(size_t)e0.y * 32 + lane];
        uint2 v1 = hh[(size_t)e1.y * 32 + lane];
        uint2 v2 = hh[(size_t)e2.y * 32 + lane];
        uint2 v3 = hh[(size_t)e3.y * 32 + lane];
        float2 f;
        f = __half22float2(*(__half2*)&v0.x); A0.x = fmaf(p0, f.x, A0.x); A0.y = fmaf(p0, f.y, A0.y);
        f = __half22float2(*(__half2*)&v0.y); A0.z = fmaf(p0, f.x, A0.z); A0.w = fmaf(p0, f.y, A0.w);
        f = __half22float2(*(__half2*)&v1.x); A1.x = fmaf(p1, f.x, A1.x); A1.y = fmaf(p1, f.y, A1.y);
        f = __half22float2(*(__half2*)&v1.y); A1.z = fmaf(p1, f.x, A1.z); A1.w = fmaf(p1, f.y, A1.w);
        f = __half22float2(*(__half2*)&v2.x); A0.x = fmaf(p2, f.x, A0.x); A0.y = fmaf(p2, f.y, A0.y);
        f = __half22float2(*(__half2*)&v2.y); A0.z = fmaf(p2, f.x, A0.z); A0.w = fmaf(p2, f.y, A0.w);
        f = __half22float2(*(__half2*)&v3.x); A1.x = fmaf(p3, f.x, A1.x); A1.y = fmaf(p3, f.y, A1.y);
        f = __half22float2(*(__half2*)&v3.y); A1.z = fmaf(p3, f.x, A1.z); A1.w = fmaf(p3, f.y, A1.w);
    }
    for (; j < deg; j++) {
        int2 e0 = ps[base + j];
        float p0 = __int_as_float(e0.x);
        uint2 v0 = hh[(size_t)e0.y * 32 + lane];
        float2 f;
        f = __half22float2(*(__half2*)&v0.x); A0.x = fmaf(p0, f.x, A0.x); A0.y = fmaf(p0, f.y, A0.y);
        f = __half22float2(*(__half2*)&v0.y); A0.z = fmaf(p0, f.x, A0.z); A0.w = fmaf(p0, f.y, A0.w);
    }

    float inv = 1.f / den;
    float4 b = ((const float4*)bias)[lane];
    float4 v;
    v.x = fmaxf((A0.x + A1.x) * inv + b.x, 0.f);
    v.y = fmaxf((A0.y + A1.y) * inv + b.y, 0.f);
    v.z = fmaxf((A0.z + A1.z) * inv + b.z, 0.f);
    v.w = fmaxf((A0.w + A1.w) * inv + b.w, 0.f);

    int g = batch[node];
    int* p = (int*)(pool + (size_t)g * HID + lane * 4);
    // values >= 0 so signed-int compare is order-preserving
    atomicMax(p + 0, __float_as_int(v.x));
    atomicMax(p + 1, __float_as_int(v.y));
    atomicMax(p + 2, __float_as_int(v.z));
    atomicMax(p + 3, __float_as_int(v.w));
}

// ---------------- launch ----------------
extern "C" void kernel_launch(void* const* d_in, const int* in_sizes, int n_in,
                              void* d_out, int out_size) {
    const float* x       = (const float*)d_in[0];   // [N, 1024]
    const float* W       = (const float*)d_in[1];   // [1024, 128]
    const float* att_src = (const float*)d_in[2];   // [128]
    const float* att_dst = (const float*)d_in[3];   // [128]
    const float* bias    = (const float*)d_in[4];   // [128]
    const int*   ei      = (const int*)d_in[5];     // [2, E]
    const int*   batch   = (const int*)d_in[6];     // [N]
    float* pool = (float*)d_out;                    // [G, 128]

    const int N = in_sizes[0] / IN_DIM;
    const int E = in_sizes[5] / 2;
    const int tot = E + N;
    const int nb = (N + 255) / 256;

    // fork-join: CSR build (stream s2) overlaps the GEMM (main stream).
    // Host-side objects only; created per call, not destroyed (few calls total;
    // destroying a capture-participating stream mid-capture breaks the graph).
    cudaStream_t s2;
    cudaStreamCreateWithFlags(&s2, cudaStreamNonBlocking);
    cudaEvent_t e1, e2;
    cudaEventCreateWithFlags(&e1, cudaEventDisableTiming);
    cudaEventCreateWithFlags(&e2, cudaEventDisableTiming);

    // common root: pool init + W half2 layout + edge count
    combo_kernel<<<(E + 255) / 256, 256>>>(W, ei, E, pool);
    cudaEventRecord(e1, 0);

    // branch A (s2): CSR offsets + scatter
    cudaStreamWaitEvent(s2, e1, 0);
    scan1_kernel<<<nb, 256, 0, s2>>>(N);
    scan23_kernel<<<nb, 256, 0, s2>>>(nb, N);
    scatter_kernel<<<(tot + 255) / 256, 256, 0, s2>>>(ei, E, N);
    cudaEventRecord(e2, s2);

    // branch B (main): fp16 mma GEMM h = x @ W (+ fused attdot)
    gemm_f16_kernel<<<(N + 127) / 128, 256>>>(x, att_src, att_dst, N);

    // join, then fused softmax + aggregate + relu + pool
    cudaStreamWaitEvent(0, e2, 0);
    gat_kernel<<<(N * 32 + 255) / 256, 256>>>(bias, batch, pool, N);
}